// round 8
// baseline (speedup 1.0000x reference)
#include <cuda_runtime.h>
#include <cuda_fp16.h>
#include <math.h>
#include <stdint.h>

// ---------------- problem constants ----------------
#define BB      2
#define SS      4096
#define HID     768
#define LAYERS  4
#define HEADS   12
#define HD      64
#define WIN     128          // one-sided window
#define MROWS   (BB*SS)      // 8192 token rows
#define QS      2304         // fused QKV row stride

// ---------------- scratch (device globals; no allocation) ----------------
__device__ __align__(256) float  g_h  [MROWS * HID];
__device__ __align__(256) __half g_hb [MROWS * HID];        // half copy of h
__device__ __align__(256) __half g_qkv[MROWS * QS];         // fused QKV (half)
__device__ __align__(256) __half g_ab [MROWS * HID];        // attention out (half)
__device__ __align__(256) float  g_t  [MROWS * HID];
__device__ __align__(256) __half g_fb [MROWS * 4 * HID];    // GELU out (half)
// preprocessed weights: transposed to [N][K], half
__device__ __align__(256) __half g_wqkv[LAYERS * QS * HID];
__device__ __align__(256) float  g_bqkv[LAYERS * QS];
__device__ __align__(256) __half g_wo [LAYERS * HID * HID];
__device__ __align__(256) __half g_wi [LAYERS * 4 * HID * HID];
__device__ __align__(256) __half g_wf [LAYERS * HID * 4 * HID];

// =======================================================================
// helpers
// =======================================================================
__device__ __forceinline__ void mma_f16(
    float& d0, float& d1, float& d2, float& d3,
    uint32_t a0, uint32_t a1, uint32_t a2, uint32_t a3,
    uint32_t b0, uint32_t b1)
{
    asm volatile(
        "mma.sync.aligned.m16n8k16.row.col.f32.f16.f16.f32 "
        "{%0,%1,%2,%3}, {%4,%5,%6,%7}, {%8,%9}, {%0,%1,%2,%3};"
        : "+f"(d0), "+f"(d1), "+f"(d2), "+f"(d3)
        : "r"(a0), "r"(a1), "r"(a2), "r"(a3), "r"(b0), "r"(b1));
}
__device__ __forceinline__ void cp16(uint32_t dst, const void* src) {
    asm volatile("cp.async.cg.shared.global [%0], [%1], 16;"
                 :: "r"(dst), "l"(src));
}

// =======================================================================
// fp16 mma.sync GEMM, cp.async 3-stage pipeline.
// C = A[M,K]*W[N,K]^T + bias.
// act=0: fp32 C.  act=1: GELU, half C.  act=2: plain, half C.
// block 128x128, BK=32, 256 threads (8 warps), warp tile 32x64.
// =======================================================================
#define TILE_BYTES (128*64)              // 8 KB per operand tile
#define STG_BYTES  (2*TILE_BYTES)        // 16 KB per stage
#define GEMM_SMEM_BYTES (3*STG_BYTES)    // 48 KB

__global__ __launch_bounds__(256, 2) void gemm_f16_kernel(
    const __half* __restrict__ A, const __half* __restrict__ Bw,
    const float* __restrict__ bias, void* __restrict__ Cout,
    int M, int N, int K, int act)
{
    extern __shared__ uint32_t smu[];
    uint32_t smem_base = (uint32_t)__cvta_generic_to_shared(smu);

    const int tid  = threadIdx.x;
    const int lane = tid & 31;
    const int wid  = tid >> 5;
    const int lm   = lane >> 2;        // 0..7
    const int lk   = lane & 3;         // 0..3
    const int warp_m = (wid >> 1) * 32;
    const int warp_n = (wid & 1) * 64;
    const int bm = blockIdx.y * 128;
    const int bn = blockIdx.x * 128;

    const __half* Ag = A  + (size_t)bm * K;
    const __half* Bg = Bw + (size_t)bn * K;

    const int r0 = tid >> 2, q0c = tid & 3;
    const int r1 = (tid + 256) >> 2, q1c = tid & 3;
    const uint32_t offA0 = (uint32_t)(r0 * 64 + (q0c ^ ((r0 >> 1) & 3)) * 16);
    const uint32_t offA1 = (uint32_t)(r1 * 64 + (q1c ^ ((r1 >> 1) & 3)) * 16);

    float acc[2][8][4];
#pragma unroll
    for (int mt = 0; mt < 2; ++mt)
#pragma unroll
        for (int nt = 0; nt < 8; ++nt)
#pragma unroll
            for (int c = 0; c < 4; ++c) acc[mt][nt][c] = 0.f;

    const int NC = K >> 5;

    auto issue = [&](int c, int stg) {
        uint32_t sA = smem_base + (uint32_t)stg * STG_BYTES;
        uint32_t sB = sA + TILE_BYTES;
        const __half* ag = Ag + c * 32;
        const __half* bg = Bg + c * 32;
        cp16(sA + offA0, ag + (size_t)r0 * K + q0c * 8);
        cp16(sA + offA1, ag + (size_t)r1 * K + q1c * 8);
        cp16(sB + offA0, bg + (size_t)r0 * K + q0c * 8);
        cp16(sB + offA1, bg + (size_t)r1 * K + q1c * 8);
    };

    issue(0, 0);
    asm volatile("cp.async.commit_group;" ::: "memory");
    if (NC > 1) issue(1, 1);
    asm volatile("cp.async.commit_group;" ::: "memory");

    const int swz = (lm >> 1) & 3;

    for (int c = 0; c < NC; ++c) {
        asm volatile("cp.async.wait_group 1;" ::: "memory");
        __syncthreads();
        if (c + 2 < NC) issue(c + 2, (c + 2) % 3);
        asm volatile("cp.async.commit_group;" ::: "memory");

        const uint32_t* sA = smu + (c % 3) * (STG_BYTES / 4);
        const uint32_t* sB = sA + TILE_BYTES / 4;
#pragma unroll
        for (int s = 0; s < 2; ++s) {
            const int q0 = 2 * s;
            const int pq0 = (q0 ^ swz) * 4 + lk;
            const int pq1 = ((q0 + 1) ^ swz) * 4 + lk;
            uint32_t a[2][4];
#pragma unroll
            for (int mt = 0; mt < 2; ++mt) {
                int m0 = warp_m + mt * 16 + lm;
                a[mt][0] = sA[m0 * 16 + pq0];
                a[mt][1] = sA[(m0 + 8) * 16 + pq0];
                a[mt][2] = sA[m0 * 16 + pq1];
                a[mt][3] = sA[(m0 + 8) * 16 + pq1];
            }
            uint32_t b[8][2];
#pragma unroll
            for (int nt = 0; nt < 8; ++nt) {
                int n0 = warp_n + nt * 8 + lm;
                b[nt][0] = sB[n0 * 16 + pq0];
                b[nt][1] = sB[n0 * 16 + pq1];
            }
#pragma unroll
            for (int mt = 0; mt < 2; ++mt)
#pragma unroll
                for (int nt = 0; nt < 8; ++nt)
                    mma_f16(acc[mt][nt][0], acc[mt][nt][1],
                            acc[mt][nt][2], acc[mt][nt][3],
                            a[mt][0], a[mt][1], a[mt][2], a[mt][3],
                            b[nt][0], b[nt][1]);
        }
    }

    // ---- epilogue ----
#pragma unroll
    for (int mt = 0; mt < 2; ++mt) {
        int row0 = bm + warp_m + mt * 16 + lm;
#pragma unroll
        for (int nt = 0; nt < 8; ++nt) {
            int col = bn + warp_n + nt * 8 + 2 * lk;
            float b0 = bias[col], b1 = bias[col + 1];
            float v0 = acc[mt][nt][0] + b0;
            float v1 = acc[mt][nt][1] + b1;
            float v2 = acc[mt][nt][2] + b0;
            float v3 = acc[mt][nt][3] + b1;
            if (act == 0) {
                float* C = (float*)Cout;
                *(float2*)(C + (size_t)row0 * N + col) = make_float2(v0, v1);
                *(float2*)(C + (size_t)(row0 + 8) * N + col) = make_float2(v2, v3);
            } else {
                if (act == 1) {
                    v0 = 0.5f * v0 * (1.0f + erff(v0 * 0.7071067811865476f));
                    v1 = 0.5f * v1 * (1.0f + erff(v1 * 0.7071067811865476f));
                    v2 = 0.5f * v2 * (1.0f + erff(v2 * 0.7071067811865476f));
                    v3 = 0.5f * v3 * (1.0f + erff(v3 * 0.7071067811865476f));
                }
                __half* C = (__half*)Cout;
                *(__half2*)(C + (size_t)row0 * N + col) = __floats2half2_rn(v0, v1);
                *(__half2*)(C + (size_t)(row0 + 8) * N + col) = __floats2half2_rn(v2, v3);
            }
        }
    }
}

// =======================================================================
// weight preprocessing: transpose fp32 [K,N] -> half [N,K]
// =======================================================================
__global__ __launch_bounds__(256) void transpose_h_kernel(
    const float* __restrict__ src, __half* __restrict__ dst, int K, int N)
{
    __shared__ float t[32][33];
    int tx = threadIdx.x, ty = threadIdx.y;      // block (32,8)
    int x = blockIdx.x * 32 + tx;                // n
    int y0 = blockIdx.y * 32;                    // k
#pragma unroll
    for (int j = 0; j < 32; j += 8)
        t[ty + j][tx] = src[(size_t)(y0 + ty + j) * N + x];
    __syncthreads();
    int n_out = blockIdx.x * 32 + ty;
#pragma unroll
    for (int j = 0; j < 32; j += 8)
        dst[(size_t)(n_out + j) * K + y0 + tx] = __float2half_rn(t[tx][ty + j]);
}

__global__ __launch_bounds__(256) void bias_qkv_kernel(
    const float* __restrict__ bq, const float* __restrict__ bk,
    const float* __restrict__ bv, float* __restrict__ bout)
{
    int idx = blockIdx.x * 256 + threadIdx.x;
    if (idx >= LAYERS * QS) return;
    int l = idx / QS, j = idx % QS;
    const float* src = (j < HID) ? bq : (j < 2 * HID) ? bk : bv;
    bout[idx] = src[(size_t)l * HID + (j % HID)];
}

// =======================================================================
// block reduction helper (768-wide rows, 256 threads)
// =======================================================================
__device__ __forceinline__ float block_sum(float v, float* sh) {
    __syncthreads();
    int lane = threadIdx.x & 31, w = threadIdx.x >> 5;
#pragma unroll
    for (int o = 16; o; o >>= 1) v += __shfl_xor_sync(0xffffffffu, v, o);
    if (lane == 0) sh[w] = v;
    __syncthreads();
    if (w == 0) {
        float t = (lane < 8) ? sh[lane] : 0.f;
#pragma unroll
        for (int o = 4; o; o >>= 1) t += __shfl_xor_sync(0xffffffffu, t, o);
        if (lane == 0) sh[0] = t;
    }
    __syncthreads();
    return sh[0];
}

// ---------------- embeddings + LN (writes fp32 + half) ----------------
__global__ __launch_bounds__(256) void embed_ln_kernel(
    const float* __restrict__ emb, const float* __restrict__ pos,
    const float* __restrict__ tok, const float* __restrict__ g,
    const float* __restrict__ b, float* __restrict__ out,
    __half* __restrict__ out_h)
{
    __shared__ float sh[8];
    int row = blockIdx.x;
    int s = row & (SS - 1);
    int tid = threadIdx.x;
    float x[3];
#pragma unroll
    for (int i = 0; i < 3; ++i) {
        int j = tid + i * 256;
        x[i] = emb[(size_t)row * HID + j] + pos[(size_t)(s + 1) * HID + j] + tok[j];
    }
    float mean = block_sum(x[0] + x[1] + x[2], sh) * (1.f / HID);
    float d2 = 0.f;
#pragma unroll
    for (int i = 0; i < 3; ++i) { float d = x[i] - mean; d2 += d * d; }
    float var = block_sum(d2, sh) * (1.f / HID);
    float rs = rsqrtf(var + 1e-12f);
#pragma unroll
    for (int i = 0; i < 3; ++i) {
        int j = tid + i * 256;
        float v = (x[i] - mean) * rs * g[j] + b[j];
        out[(size_t)row * HID + j] = v;
        out_h[(size_t)row * HID + j] = __float2half_rn(v);
    }
}

// ---------------- residual add + LN (writes fp32 + half) -------------
__global__ __launch_bounds__(256) void add_ln_kernel(
    const float* __restrict__ hin, const float* __restrict__ xin,
    const float* __restrict__ g, const float* __restrict__ b,
    float* __restrict__ out, __half* __restrict__ out_h)
{
    __shared__ float sh[8];
    int row = blockIdx.x;
    int tid = threadIdx.x;
    float x[3];
#pragma unroll
    for (int i = 0; i < 3; ++i) {
        int j = tid + i * 256;
        x[i] = hin[(size_t)row * HID + j] + xin[(size_t)row * HID + j];
    }
    float mean = block_sum(x[0] + x[1] + x[2], sh) * (1.f / HID);
    float d2 = 0.f;
#pragma unroll
    for (int i = 0; i < 3; ++i) { float d = x[i] - mean; d2 += d * d; }
    float var = block_sum(d2, sh) * (1.f / HID);
    float rs = rsqrtf(var + 1e-12f);
#pragma unroll
    for (int i = 0; i < 3; ++i) {
        int j = tid + i * 256;
        float v = (x[i] - mean) * rs * g[j] + b[j];
        out[(size_t)row * HID + j] = v;
        out_h[(size_t)row * HID + j] = __float2half_rn(v);
    }
}

// =======================================================================
// tensor-core banded flash attention.
// grid (S/64, H, B), 128 threads (4 warps). Query tile 64 (16/warp),
// 5 key tiles of 64. QKV half, fused layout [row][QS].
// S = Q K^T via m16n8k16, P kept in registers, PV via m16n8k16.
// =======================================================================
#define KV_PITCH 72
__global__ __launch_bounds__(128) void attn_tc_kernel(
    const __half* __restrict__ QKV, const int* __restrict__ am,
    __half* __restrict__ Aout)
{
    __shared__ __half Qs [64 * KV_PITCH];
    __shared__ __half Ks [64 * KV_PITCH];
    __shared__ __half Vst[64 * KV_PITCH];   // transposed: [d][key]
    __shared__ int kval[64];

    const int tid  = threadIdx.x;
    const int lane = tid & 31;
    const int w    = tid >> 5;          // warp 0..3
    const int lm   = lane >> 2;         // 0..7
    const int lk   = lane & 3;          // 0..3
    const int q0 = blockIdx.x * 64, h = blockIdx.y, b = blockIdx.z;
    const size_t base  = ((size_t)b * SS) * QS + (size_t)h * HD;
    const size_t baseO = ((size_t)b * SS) * HID + (size_t)h * HD;

    // ---- stage Q tile [64 q][64 d] ----
#pragma unroll
    for (int it = 0; it < 4; ++it) {
        int idx = tid + it * 128;          // 0..511
        int r = idx >> 3, c8 = (idx & 7) * 8;
        *(float4*)&Qs[r * KV_PITCH + c8] =
            *(const float4*)(QKV + base + (size_t)(q0 + r) * QS + c8);
    }
    __syncthreads();

    // ---- Q fragments (row = w*16 + lm / +8) ----
    uint32_t qf[4][4];
    {
        int r0 = w * 16 + lm, r1 = r0 + 8;
#pragma unroll
        for (int s = 0; s < 4; ++s) {
            qf[s][0] = *(const uint32_t*)&Qs[r0 * KV_PITCH + 16 * s + 2 * lk];
            qf[s][1] = *(const uint32_t*)&Qs[r1 * KV_PITCH + 16 * s + 2 * lk];
            qf[s][2] = *(const uint32_t*)&Qs[r0 * KV_PITCH + 16 * s + 8 + 2 * lk];
            qf[s][3] = *(const uint32_t*)&Qs[r1 * KV_PITCH + 16 * s + 8 + 2 * lk];
        }
    }

    const int qi0 = q0 + w * 16 + lm;
    const int qi1 = qi0 + 8;

    float m0 = -INFINITY, m1 = -INFINITY, l0 = 0.f, l1 = 0.f;
    float O[8][4];
#pragma unroll
    for (int t = 0; t < 8; ++t)
#pragma unroll
        for (int c = 0; c < 4; ++c) O[t][c] = 0.f;

    for (int kt = 0; kt < 5; ++kt) {
        const int ks = q0 - 128 + kt * 64;
        __syncthreads();   // prior-iter Ks/Vst reads complete
#pragma unroll
        for (int it = 0; it < 4; ++it) {
            int idx = tid + it * 128;
            int r = idx >> 3, c8 = (idx & 7) * 8;
            int kj = ks + r;
            float4 kv = make_float4(0.f, 0.f, 0.f, 0.f);
            float4 vv = make_float4(0.f, 0.f, 0.f, 0.f);
            if ((unsigned)kj < (unsigned)SS) {
                kv = *(const float4*)(QKV + base + (size_t)kj * QS + HID + c8);
                vv = *(const float4*)(QKV + base + (size_t)kj * QS + 2 * HID + c8);
            }
            *(float4*)&Ks[r * KV_PITCH + c8] = kv;
            const __half* vh = (const __half*)&vv;
#pragma unroll
            for (int j = 0; j < 8; ++j)
                Vst[(c8 + j) * KV_PITCH + r] = vh[j];
        }
        if (tid < 64) {
            int kj = ks + tid;
            kval[tid] = ((unsigned)kj < (unsigned)SS) && (am[(size_t)b * SS + kj] != 0);
        }
        __syncthreads();

        // ---- S = Q K^T ----
        float sacc[8][4];
#pragma unroll
        for (int t = 0; t < 8; ++t) {
#pragma unroll
            for (int c = 0; c < 4; ++c) sacc[t][c] = 0.f;
            int nr = 8 * t + lm;
#pragma unroll
            for (int s = 0; s < 4; ++s) {
                uint32_t b0 = *(const uint32_t*)&Ks[nr * KV_PITCH + 16 * s + 2 * lk];
                uint32_t b1 = *(const uint32_t*)&Ks[nr * KV_PITCH + 16 * s + 8 + 2 * lk];
                mma_f16(sacc[t][0], sacc[t][1], sacc[t][2], sacc[t][3],
                        qf[s][0], qf[s][1], qf[s][2], qf[s][3], b0, b1);
            }
        }

        // ---- mask + scale + row max ----
        float rm0 = -INFINITY, rm1 = -INFINITY;
#pragma unroll
        for (int t = 0; t < 8; ++t) {
            int kc = 8 * t + 2 * lk;
            int kj0 = ks + kc, kj1 = kj0 + 1;
            bool v0 = kval[kc] != 0, v1 = kval[kc + 1] != 0;
            float s00 = (v0 && abs(kj0 - qi0) <= WIN) ? sacc[t][0] * 0.125f : -1e9f;
            float s01 = (v1 && abs(kj1 - qi0) <= WIN) ? sacc[t][1] * 0.125f : -1e9f;
            float s10 = (v0 && abs(kj0 - qi1) <= WIN) ? sacc[t][2] * 0.125f : -1e9f;
            float s11 = (v1 && abs(kj1 - qi1) <= WIN) ? sacc[t][3] * 0.125f : -1e9f;
            sacc[t][0] = s00; sacc[t][1] = s01; sacc[t][2] = s10; sacc[t][3] = s11;
            rm0 = fmaxf(rm0, fmaxf(s00, s01));
            rm1 = fmaxf(rm1, fmaxf(s10, s11));
        }
        rm0 = fmaxf(rm0, __shfl_xor_sync(0xffffffffu, rm0, 1));
        rm0 = fmaxf(rm0, __shfl_xor_sync(0xffffffffu, rm0, 2));
        rm1 = fmaxf(rm1, __shfl_xor_sync(0xffffffffu, rm1, 1));
        rm1 = fmaxf(rm1, __shfl_xor_sync(0xffffffffu, rm1, 2));

        float mn0 = fmaxf(m0, rm0), mn1 = fmaxf(m1, rm1);
        float sc0 = __expf(m0 - mn0), sc1 = __expf(m1 - mn1);
        m0 = mn0; m1 = mn1;

        float rs0 = 0.f, rs1 = 0.f;
        uint32_t pf[8][2];
#pragma unroll
        for (int t = 0; t < 8; ++t) {
            float p00 = __expf(sacc[t][0] - mn0);
            float p01 = __expf(sacc[t][1] - mn0);
            float p10 = __expf(sacc[t][2] - mn1);
            float p11 = __expf(sacc[t][3] - mn1);
            rs0 += p00 + p01; rs1 += p10 + p11;
            __half2 h0 = __floats2half2_rn(p00, p01);
            __half2 h1 = __floats2half2_rn(p10, p11);
            pf[t][0] = *(uint32_t*)&h0;
            pf[t][1] = *(uint32_t*)&h1;
        }
        rs0 += __shfl_xor_sync(0xffffffffu, rs0, 1);
        rs0 += __shfl_xor_sync(0xffffffffu, rs0, 2);
        rs1 += __shfl_xor_sync(0xffffffffu, rs1, 1);
        rs1 += __shfl_xor_sync(0xffffffffu, rs1, 2);
        l0 = l0 * sc0 + rs0;
        l1 = l1 * sc1 + rs1;
#pragma unroll
        for (int t = 0; t < 8; ++t) {
            O[t][0] *= sc0; O[t][1] *= sc0;
            O[t][2] *= sc1; O[t][3] *= sc1;
        }

        // ---- O += P V ----
#pragma unroll
        for (int s = 0; s < 4; ++s) {
            uint32_t a0 = pf[2 * s][0], a1 = pf[2 * s][1];
            uint32_t a2 = pf[2 * s + 1][0], a3 = pf[2 * s + 1][1];
#pragma unroll
            for (int t = 0; t < 8; ++t) {
                int dr = 8 * t + lm;
                uint32_t b0 = *(const uint32_t*)&Vst[dr * KV_PITCH + 16 * s + 2 * lk];
                uint32_t b1 = *(const uint32_t*)&Vst[dr * KV_PITCH + 16 * s + 8 + 2 * lk];
                mma_f16(O[t][0], O[t][1], O[t][2], O[t][3],
                        a0, a1, a2, a3, b0, b1);
            }
        }
    }

    float rl0 = (l0 > 0.f) ? (1.f / l0) : 0.f;
    float rl1 = (l1 > 0.f) ? (1.f / l1) : 0.f;
#pragma unroll
    for (int t = 0; t < 8; ++t) {
        int col = 8 * t + 2 * lk;
        *(__half2*)(Aout + baseO + (size_t)qi0 * HID + col)
            = __floats2half2_rn(O[t][0] * rl0, O[t][1] * rl0);
        *(__half2*)(Aout + baseO + (size_t)qi1 * HID + col)
            = __floats2half2_rn(O[t][2] * rl1, O[t][3] * rl1);
    }
}

// ---------------- final projection + sigmoid ----------------
__global__ __launch_bounds__(256) void final_kernel(
    const float* __restrict__ h, const float* __restrict__ Wp,
    const float* __restrict__ bp, float* __restrict__ out)
{
    int gtid = blockIdx.x * 256 + threadIdx.x;
    int row = gtid >> 5;
    int lane = gtid & 31;
    if (row >= MROWS) return;
    float s = 0.f;
    for (int k = lane; k < HID; k += 32)
        s = fmaf(h[(size_t)row * HID + k], Wp[k], s);
#pragma unroll
    for (int o = 16; o; o >>= 1) s += __shfl_xor_sync(0xffffffffu, s, o);
    if (lane == 0)
        out[row] = 1.f / (1.f + expf(-(s + bp[0])));
}

// ---------------- host orchestration ----------------
extern "C" void kernel_launch(void* const* d_in, const int* in_sizes, int n_in,
                              void* d_out, int out_size)
{
    const float* emb     = (const float*)d_in[0];
    const int*   amask   = (const int*)  d_in[1];
    const float* pos     = (const float*)d_in[2];
    const float* tok     = (const float*)d_in[3];
    const float* eln_g   = (const float*)d_in[4];
    const float* eln_b   = (const float*)d_in[5];
    const float* Wq      = (const float*)d_in[6];
    const float* bq      = (const float*)d_in[7];
    const float* Wk      = (const float*)d_in[8];
    const float* bk      = (const float*)d_in[9];
    const float* Wv      = (const float*)d_in[10];
    const float* bv      = (const float*)d_in[11];
    const float* Wo      = (const float*)d_in[12];
    const float* bo      = (const float*)d_in[13];
    const float* ln1_g   = (const float*)d_in[14];
    const float* ln1_b   = (const float*)d_in[15];
    const float* Wi      = (const float*)d_in[16];
    const float* bi      = (const float*)d_in[17];
    const float* Wf      = (const float*)d_in[18];
    const float* bf      = (const float*)d_in[19];
    const float* ln2_g   = (const float*)d_in[20];
    const float* ln2_b   = (const float*)d_in[21];
    const float* Wp      = (const float*)d_in[22];
    const float* bp      = (const float*)d_in[23];

    float  *h_, *t_, *bqkv_;
    __half *hb_, *qkv_, *ab_, *fb_, *wqkv_, *wo_, *wi_, *wf_;
    cudaGetSymbolAddress((void**)&h_,   g_h);
    cudaGetSymbolAddress((void**)&hb_,  g_hb);
    cudaGetSymbolAddress((void**)&qkv_, g_qkv);
    cudaGetSymbolAddress((void**)&ab_,  g_ab);
    cudaGetSymbolAddress((void**)&t_,   g_t);
    cudaGetSymbolAddress((void**)&fb_,  g_fb);
    cudaGetSymbolAddress((void**)&wqkv_, g_wqkv);
    cudaGetSymbolAddress((void**)&bqkv_, g_bqkv);
    cudaGetSymbolAddress((void**)&wo_,  g_wo);
    cudaGetSymbolAddress((void**)&wi_,  g_wi);
    cudaGetSymbolAddress((void**)&wf_,  g_wf);

    cudaFuncSetAttribute(gemm_f16_kernel,
                         cudaFuncAttributeMaxDynamicSharedMemorySize, GEMM_SMEM_BYTES);

    const size_t WSQ   = (size_t)HID * HID;
    const size_t WSI   = (size_t)HID * 4 * HID;
    const size_t WSQKV = (size_t)QS * HID;

    // ---- weight preprocessing: transpose + fp16 round ----
    {
        dim3 blk(32, 8);
        for (int l = 0; l < LAYERS; ++l) {
            dim3 gsq(HID / 32, HID / 32);
            transpose_h_kernel<<<gsq, blk>>>(Wq + l * WSQ, wqkv_ + l * WSQKV, HID, HID);
            transpose_h_kernel<<<gsq, blk>>>(Wk + l * WSQ, wqkv_ + l * WSQKV + (size_t)HID * HID, HID, HID);
            transpose_h_kernel<<<gsq, blk>>>(Wv + l * WSQ, wqkv_ + l * WSQKV + (size_t)2 * HID * HID, HID, HID);
            transpose_h_kernel<<<gsq, blk>>>(Wo + l * WSQ, wo_ + l * WSQ, HID, HID);
            dim3 gi(4 * HID / 32, HID / 32);
            transpose_h_kernel<<<gi, blk>>>(Wi + l * WSI, wi_ + l * WSI, HID, 4 * HID);
            dim3 gf(HID / 32, 4 * HID / 32);
            transpose_h_kernel<<<gf, blk>>>(Wf + l * WSI, wf_ + l * WSI, 4 * HID, HID);
        }
        bias_qkv_kernel<<<(LAYERS * QS + 255) / 256, 256>>>(bq, bk, bv, bqkv_);
    }

    embed_ln_kernel<<<MROWS, 256>>>(emb, pos, tok, eln_g, eln_b, h_, hb_);

    for (int l = 0; l < LAYERS; ++l) {
        dim3 gqkv(QS / 128, MROWS / 128);         // (18, 64)
        gemm_f16_kernel<<<gqkv, 256, GEMM_SMEM_BYTES>>>(
            hb_, wqkv_ + l * WSQKV, bqkv_ + (size_t)l * QS, qkv_,
            MROWS, QS, HID, 2);

        dim3 ga(SS / 64, HEADS, BB);
        attn_tc_kernel<<<ga, 128>>>(qkv_, amask, ab_);

        dim3 g1(HID / 128, MROWS / 128);          // (6, 64)
        gemm_f16_kernel<<<g1, 256, GEMM_SMEM_BYTES>>>(
            ab_, wo_ + l * WSQ, bo + (size_t)l * HID, t_, MROWS, HID, HID, 0);
        add_ln_kernel<<<MROWS, 256>>>(h_, t_, ln1_g + l * HID, ln1_b + l * HID, h_, hb_);

        dim3 g2(4 * HID / 128, MROWS / 128);      // (24, 64)
        gemm_f16_kernel<<<g2, 256, GEMM_SMEM_BYTES>>>(
            hb_, wi_ + l * WSI, bi + (size_t)l * 4 * HID, fb_,
            MROWS, 4 * HID, HID, 1);
        gemm_f16_kernel<<<g1, 256, GEMM_SMEM_BYTES>>>(
            fb_, wf_ + l * WSI, bf + (size_t)l * HID, t_, MROWS, HID, 4 * HID, 0);
        add_ln_kernel<<<MROWS, 256>>>(h_, t_, ln2_g + l * HID, ln2_b + l * HID, h_, hb_);
    }

    final_kernel<<<(MROWS * 32 + 255) / 256, 256>>>(h_, Wp, bp, (float*)d_out);
}

// round 9
// speedup vs baseline: 1.6075x; 1.6075x over previous
#include <cuda_runtime.h>
#include <cuda_fp16.h>
#include <math.h>
#include <stdint.h>

// ---------------- problem constants ----------------
#define BB      2
#define SS      4096
#define HID     768
#define LAYERS  4
#define HEADS   12
#define HD      64
#define WIN     128          // one-sided window
#define MROWS   (BB*SS)      // 8192 token rows
#define QS      2304         // fused QKV row stride

// ---------------- scratch (device globals; no allocation) ----------------
__device__ __align__(256) float  g_h  [MROWS * HID];
__device__ __align__(256) __half g_hb [MROWS * HID];
__device__ __align__(256) __half g_qkv[MROWS * QS];
__device__ __align__(256) __half g_ab [MROWS * HID];
__device__ __align__(256) float  g_t  [MROWS * HID];
__device__ __align__(256) __half g_fb [MROWS * 4 * HID];
// preprocessed weights: transposed to [N][K], half
__device__ __align__(256) __half g_wqkv[LAYERS * QS * HID];
__device__ __align__(256) float  g_bqkv[LAYERS * QS];
__device__ __align__(256) __half g_wo [LAYERS * HID * HID];
__device__ __align__(256) __half g_wi [LAYERS * 4 * HID * HID];
__device__ __align__(256) __half g_wf [LAYERS * HID * 4 * HID];

// =======================================================================
// helpers
// =======================================================================
__device__ __forceinline__ void mma_f16(
    float& d0, float& d1, float& d2, float& d3,
    uint32_t a0, uint32_t a1, uint32_t a2, uint32_t a3,
    uint32_t b0, uint32_t b1)
{
    asm volatile(
        "mma.sync.aligned.m16n8k16.row.col.f32.f16.f16.f32 "
        "{%0,%1,%2,%3}, {%4,%5,%6,%7}, {%8,%9}, {%0,%1,%2,%3};"
        : "+f"(d0), "+f"(d1), "+f"(d2), "+f"(d3)
        : "r"(a0), "r"(a1), "r"(a2), "r"(a3), "r"(b0), "r"(b1));
}
__device__ __forceinline__ void cp16(uint32_t dst, const void* src) {
    asm volatile("cp.async.cg.shared.global [%0], [%1], 16;"
                 :: "r"(dst), "l"(src));
}
__device__ __forceinline__ void ldsm_x4(uint32_t* r, uint32_t addr) {
    asm volatile("ldmatrix.sync.aligned.m8n8.x4.shared.b16 {%0,%1,%2,%3}, [%4];"
        : "=r"(r[0]), "=r"(r[1]), "=r"(r[2]), "=r"(r[3]) : "r"(addr));
}
__device__ __forceinline__ void ldsm_x4_t(uint32_t* r, uint32_t addr) {
    asm volatile("ldmatrix.sync.aligned.m8n8.x4.trans.shared.b16 {%0,%1,%2,%3}, [%4];"
        : "=r"(r[0]), "=r"(r[1]), "=r"(r[2]), "=r"(r[3]) : "r"(addr));
}

// =======================================================================
// fp16 mma.sync GEMM, cp.async 3-stage pipeline. (unchanged from R7)
// act=0: fp32 C.  act=1: GELU, half C.  act=2: plain, half C.
// =======================================================================
#define TILE_BYTES (128*64)
#define STG_BYTES  (2*TILE_BYTES)
#define GEMM_SMEM_BYTES (3*STG_BYTES)    // 48 KB

__global__ __launch_bounds__(256, 2) void gemm_f16_kernel(
    const __half* __restrict__ A, const __half* __restrict__ Bw,
    const float* __restrict__ bias, void* __restrict__ Cout,
    int M, int N, int K, int act)
{
    extern __shared__ uint32_t smu[];
    uint32_t smem_base = (uint32_t)__cvta_generic_to_shared(smu);

    const int tid  = threadIdx.x;
    const int lane = tid & 31;
    const int wid  = tid >> 5;
    const int lm   = lane >> 2;
    const int lk   = lane & 3;
    const int warp_m = (wid >> 1) * 32;
    const int warp_n = (wid & 1) * 64;
    const int bm = blockIdx.y * 128;
    const int bn = blockIdx.x * 128;

    const __half* Ag = A  + (size_t)bm * K;
    const __half* Bg = Bw + (size_t)bn * K;

    const int r0 = tid >> 2, q0c = tid & 3;
    const int r1 = (tid + 256) >> 2, q1c = tid & 3;
    const uint32_t offA0 = (uint32_t)(r0 * 64 + (q0c ^ ((r0 >> 1) & 3)) * 16);
    const uint32_t offA1 = (uint32_t)(r1 * 64 + (q1c ^ ((r1 >> 1) & 3)) * 16);

    float acc[2][8][4];
#pragma unroll
    for (int mt = 0; mt < 2; ++mt)
#pragma unroll
        for (int nt = 0; nt < 8; ++nt)
#pragma unroll
            for (int c = 0; c < 4; ++c) acc[mt][nt][c] = 0.f;

    const int NC = K >> 5;

    auto issue = [&](int c, int stg) {
        uint32_t sA = smem_base + (uint32_t)stg * STG_BYTES;
        uint32_t sB = sA + TILE_BYTES;
        const __half* ag = Ag + c * 32;
        const __half* bg = Bg + c * 32;
        cp16(sA + offA0, ag + (size_t)r0 * K + q0c * 8);
        cp16(sA + offA1, ag + (size_t)r1 * K + q1c * 8);
        cp16(sB + offA0, bg + (size_t)r0 * K + q0c * 8);
        cp16(sB + offA1, bg + (size_t)r1 * K + q1c * 8);
    };

    issue(0, 0);
    asm volatile("cp.async.commit_group;" ::: "memory");
    if (NC > 1) issue(1, 1);
    asm volatile("cp.async.commit_group;" ::: "memory");

    const int swz = (lm >> 1) & 3;

    for (int c = 0; c < NC; ++c) {
        asm volatile("cp.async.wait_group 1;" ::: "memory");
        __syncthreads();
        if (c + 2 < NC) issue(c + 2, (c + 2) % 3);
        asm volatile("cp.async.commit_group;" ::: "memory");

        const uint32_t* sA = smu + (c % 3) * (STG_BYTES / 4);
        const uint32_t* sB = sA + TILE_BYTES / 4;
#pragma unroll
        for (int s = 0; s < 2; ++s) {
            const int q0 = 2 * s;
            const int pq0 = (q0 ^ swz) * 4 + lk;
            const int pq1 = ((q0 + 1) ^ swz) * 4 + lk;
            uint32_t a[2][4];
#pragma unroll
            for (int mt = 0; mt < 2; ++mt) {
                int m0 = warp_m + mt * 16 + lm;
                a[mt][0] = sA[m0 * 16 + pq0];
                a[mt][1] = sA[(m0 + 8) * 16 + pq0];
                a[mt][2] = sA[m0 * 16 + pq1];
                a[mt][3] = sA[(m0 + 8) * 16 + pq1];
            }
            uint32_t b[8][2];
#pragma unroll
            for (int nt = 0; nt < 8; ++nt) {
                int n0 = warp_n + nt * 8 + lm;
                b[nt][0] = sB[n0 * 16 + pq0];
                b[nt][1] = sB[n0 * 16 + pq1];
            }
#pragma unroll
            for (int mt = 0; mt < 2; ++mt)
#pragma unroll
                for (int nt = 0; nt < 8; ++nt)
                    mma_f16(acc[mt][nt][0], acc[mt][nt][1],
                            acc[mt][nt][2], acc[mt][nt][3],
                            a[mt][0], a[mt][1], a[mt][2], a[mt][3],
                            b[nt][0], b[nt][1]);
        }
    }

#pragma unroll
    for (int mt = 0; mt < 2; ++mt) {
        int row0 = bm + warp_m + mt * 16 + lm;
#pragma unroll
        for (int nt = 0; nt < 8; ++nt) {
            int col = bn + warp_n + nt * 8 + 2 * lk;
            float b0 = bias[col], b1 = bias[col + 1];
            float v0 = acc[mt][nt][0] + b0;
            float v1 = acc[mt][nt][1] + b1;
            float v2 = acc[mt][nt][2] + b0;
            float v3 = acc[mt][nt][3] + b1;
            if (act == 0) {
                float* C = (float*)Cout;
                *(float2*)(C + (size_t)row0 * N + col) = make_float2(v0, v1);
                *(float2*)(C + (size_t)(row0 + 8) * N + col) = make_float2(v2, v3);
            } else {
                if (act == 1) {
                    v0 = 0.5f * v0 * (1.0f + erff(v0 * 0.7071067811865476f));
                    v1 = 0.5f * v1 * (1.0f + erff(v1 * 0.7071067811865476f));
                    v2 = 0.5f * v2 * (1.0f + erff(v2 * 0.7071067811865476f));
                    v3 = 0.5f * v3 * (1.0f + erff(v3 * 0.7071067811865476f));
                }
                __half* C = (__half*)Cout;
                *(__half2*)(C + (size_t)row0 * N + col) = __floats2half2_rn(v0, v1);
                *(__half2*)(C + (size_t)(row0 + 8) * N + col) = __floats2half2_rn(v2, v3);
            }
        }
    }
}

// =======================================================================
// weight preprocessing: transpose fp32 [K,N] -> half [N,K], batched layers
// =======================================================================
__global__ __launch_bounds__(256) void transpose_h_kernel(
    const float* __restrict__ src, __half* __restrict__ dst, int K, int N,
    size_t sstride, size_t dstride)
{
    __shared__ float t[32][33];
    src += (size_t)blockIdx.z * sstride;
    dst += (size_t)blockIdx.z * dstride;
    int tx = threadIdx.x, ty = threadIdx.y;
    int x = blockIdx.x * 32 + tx;
    int y0 = blockIdx.y * 32;
#pragma unroll
    for (int j = 0; j < 32; j += 8)
        t[ty + j][tx] = src[(size_t)(y0 + ty + j) * N + x];
    __syncthreads();
    int n_out = blockIdx.x * 32 + ty;
#pragma unroll
    for (int j = 0; j < 32; j += 8)
        dst[(size_t)(n_out + j) * K + y0 + tx] = __float2half_rn(t[tx][ty + j]);
}

__global__ __launch_bounds__(256) void bias_qkv_kernel(
    const float* __restrict__ bq, const float* __restrict__ bk,
    const float* __restrict__ bv, float* __restrict__ bout)
{
    int idx = blockIdx.x * 256 + threadIdx.x;
    if (idx >= LAYERS * QS) return;
    int l = idx / QS, j = idx % QS;
    const float* src = (j < HID) ? bq : (j < 2 * HID) ? bk : bv;
    bout[idx] = src[(size_t)l * HID + (j % HID)];
}

// =======================================================================
// block reduction helper
// =======================================================================
__device__ __forceinline__ float block_sum(float v, float* sh) {
    __syncthreads();
    int lane = threadIdx.x & 31, w = threadIdx.x >> 5;
#pragma unroll
    for (int o = 16; o; o >>= 1) v += __shfl_xor_sync(0xffffffffu, v, o);
    if (lane == 0) sh[w] = v;
    __syncthreads();
    if (w == 0) {
        float t = (lane < 8) ? sh[lane] : 0.f;
#pragma unroll
        for (int o = 4; o; o >>= 1) t += __shfl_xor_sync(0xffffffffu, t, o);
        if (lane == 0) sh[0] = t;
    }
    __syncthreads();
    return sh[0];
}

// ---------------- embeddings + LN ----------------
__global__ __launch_bounds__(256) void embed_ln_kernel(
    const float* __restrict__ emb, const float* __restrict__ pos,
    const float* __restrict__ tok, const float* __restrict__ g,
    const float* __restrict__ b, float* __restrict__ out,
    __half* __restrict__ out_h)
{
    __shared__ float sh[8];
    int row = blockIdx.x;
    int s = row & (SS - 1);
    int tid = threadIdx.x;
    float x[3];
#pragma unroll
    for (int i = 0; i < 3; ++i) {
        int j = tid + i * 256;
        x[i] = emb[(size_t)row * HID + j] + pos[(size_t)(s + 1) * HID + j] + tok[j];
    }
    float mean = block_sum(x[0] + x[1] + x[2], sh) * (1.f / HID);
    float d2 = 0.f;
#pragma unroll
    for (int i = 0; i < 3; ++i) { float d = x[i] - mean; d2 += d * d; }
    float var = block_sum(d2, sh) * (1.f / HID);
    float rs = rsqrtf(var + 1e-12f);
#pragma unroll
    for (int i = 0; i < 3; ++i) {
        int j = tid + i * 256;
        float v = (x[i] - mean) * rs * g[j] + b[j];
        out[(size_t)row * HID + j] = v;
        out_h[(size_t)row * HID + j] = __float2half_rn(v);
    }
}

// ---------------- residual add + LN ----------------
__global__ __launch_bounds__(256) void add_ln_kernel(
    const float* __restrict__ hin, const float* __restrict__ xin,
    const float* __restrict__ g, const float* __restrict__ b,
    float* __restrict__ out, __half* __restrict__ out_h)
{
    __shared__ float sh[8];
    int row = blockIdx.x;
    int tid = threadIdx.x;
    float x[3];
#pragma unroll
    for (int i = 0; i < 3; ++i) {
        int j = tid + i * 256;
        x[i] = hin[(size_t)row * HID + j] + xin[(size_t)row * HID + j];
    }
    float mean = block_sum(x[0] + x[1] + x[2], sh) * (1.f / HID);
    float d2 = 0.f;
#pragma unroll
    for (int i = 0; i < 3; ++i) { float d = x[i] - mean; d2 += d * d; }
    float var = block_sum(d2, sh) * (1.f / HID);
    float rs = rsqrtf(var + 1e-12f);
#pragma unroll
    for (int i = 0; i < 3; ++i) {
        int j = tid + i * 256;
        float v = (x[i] - mean) * rs * g[j] + b[j];
        out[(size_t)row * HID + j] = v;
        out_h[(size_t)row * HID + j] = __float2half_rn(v);
    }
}

// =======================================================================
// tensor-core banded flash attention, ldmatrix edition.
// grid (S/64, H, B), 128 threads (4 warps), 64-query tile, 5x64 key tiles.
// K,V staged naturally [row][d]; fragments via ldmatrix(.trans).
// =======================================================================
#define KV_PITCH 72
__global__ __launch_bounds__(128) void attn_tc_kernel(
    const __half* __restrict__ QKV, const int* __restrict__ am,
    __half* __restrict__ Aout)
{
    __shared__ __half Qs[64 * KV_PITCH];
    __shared__ __half Ks[64 * KV_PITCH];
    __shared__ __half Vs[64 * KV_PITCH];
    __shared__ int kval[64];

    const int tid  = threadIdx.x;
    const int lane = tid & 31;
    const int w    = tid >> 5;
    const int lm   = lane >> 2;
    const int lk   = lane & 3;
    const int jr   = lane & 7;         // ldmatrix row within 8x8
    const int jg   = lane >> 3;        // ldmatrix matrix index 0..3
    const int q0 = blockIdx.x * 64, h = blockIdx.y, b = blockIdx.z;
    const size_t base  = ((size_t)b * SS) * QS + (size_t)h * HD;
    const size_t baseO = ((size_t)b * SS) * HID + (size_t)h * HD;

    const uint32_t qsm = (uint32_t)__cvta_generic_to_shared(Qs);
    const uint32_t ksm = (uint32_t)__cvta_generic_to_shared(Ks);
    const uint32_t vsm = (uint32_t)__cvta_generic_to_shared(Vs);

    // ---- stage Q tile [64 q][64 d] ----
#pragma unroll
    for (int it = 0; it < 4; ++it) {
        int idx = tid + it * 128;
        int r = idx >> 3, c8 = (idx & 7) * 8;
        *(float4*)&Qs[r * KV_PITCH + c8] =
            *(const float4*)(QKV + base + (size_t)(q0 + r) * QS + c8);
    }
    __syncthreads();

    // ---- Q fragments via ldmatrix.x4:
    //  m0: rows r0..r0+7   k 0..7   -> a0
    //  m1: rows r0+8..+15  k 0..7   -> a1
    //  m2: rows r0..r0+7   k 8..15  -> a2
    //  m3: rows r0+8..+15  k 8..15  -> a3
    uint32_t qf[4][4];
    {
        int row = w * 16 + ((jg & 1) << 3) + jr;
        int coff = (jg >> 1) << 3;
#pragma unroll
        for (int s = 0; s < 4; ++s)
            ldsm_x4(qf[s], qsm + (uint32_t)(row * KV_PITCH + 16 * s + coff) * 2);
    }

    const int qi0 = q0 + w * 16 + lm;
    const int qi1 = qi0 + 8;

    float m0 = -INFINITY, m1 = -INFINITY, l0 = 0.f, l1 = 0.f;
    float O[8][4];
#pragma unroll
    for (int t = 0; t < 8; ++t)
#pragma unroll
        for (int c = 0; c < 4; ++c) O[t][c] = 0.f;

    for (int kt = 0; kt < 5; ++kt) {
        const int ks = q0 - 128 + kt * 64;
        __syncthreads();
#pragma unroll
        for (int it = 0; it < 4; ++it) {
            int idx = tid + it * 128;
            int r = idx >> 3, c8 = (idx & 7) * 8;
            int kj = ks + r;
            float4 kv = make_float4(0.f, 0.f, 0.f, 0.f);
            float4 vv = make_float4(0.f, 0.f, 0.f, 0.f);
            if ((unsigned)kj < (unsigned)SS) {
                kv = *(const float4*)(QKV + base + (size_t)kj * QS + HID + c8);
                vv = *(const float4*)(QKV + base + (size_t)kj * QS + 2 * HID + c8);
            }
            *(float4*)&Ks[r * KV_PITCH + c8] = kv;
            *(float4*)&Vs[r * KV_PITCH + c8] = vv;
        }
        if (tid < 64) {
            int kj = ks + tid;
            kval[tid] = ((unsigned)kj < (unsigned)SS) && (am[(size_t)b * SS + kj] != 0);
        }
        __syncthreads();

        // ---- S = Q K^T ----
        float sacc[8][4];
#pragma unroll
        for (int t = 0; t < 8; ++t) {
#pragma unroll
            for (int c = 0; c < 4; ++c) sacc[t][c] = 0.f;
            // kf via 2x ldmatrix.x4: matrices = key rows 8t..8t+7,
            // dim cols {0-7,8-15,16-23,24-31} then {32-39,...,56-63}
            uint32_t kf[8];
            int krow = 8 * t + jr;
            ldsm_x4(kf,     ksm + (uint32_t)(krow * KV_PITCH + 8 * jg) * 2);
            ldsm_x4(kf + 4, ksm + (uint32_t)(krow * KV_PITCH + 32 + 8 * jg) * 2);
#pragma unroll
            for (int s = 0; s < 4; ++s)
                mma_f16(sacc[t][0], sacc[t][1], sacc[t][2], sacc[t][3],
                        qf[s][0], qf[s][1], qf[s][2], qf[s][3],
                        kf[2 * s], kf[2 * s + 1]);
        }

        // ---- mask + scale + row max ----
        float rm0 = -INFINITY, rm1 = -INFINITY;
#pragma unroll
        for (int t = 0; t < 8; ++t) {
            int kc = 8 * t + 2 * lk;
            int kj0 = ks + kc, kj1 = kj0 + 1;
            bool v0 = kval[kc] != 0, v1 = kval[kc + 1] != 0;
            float s00 = (v0 && abs(kj0 - qi0) <= WIN) ? sacc[t][0] * 0.125f : -1e9f;
            float s01 = (v1 && abs(kj1 - qi0) <= WIN) ? sacc[t][1] * 0.125f : -1e9f;
            float s10 = (v0 && abs(kj0 - qi1) <= WIN) ? sacc[t][2] * 0.125f : -1e9f;
            float s11 = (v1 && abs(kj1 - qi1) <= WIN) ? sacc[t][3] * 0.125f : -1e9f;
            sacc[t][0] = s00; sacc[t][1] = s01; sacc[t][2] = s10; sacc[t][3] = s11;
            rm0 = fmaxf(rm0, fmaxf(s00, s01));
            rm1 = fmaxf(rm1, fmaxf(s10, s11));
        }
        rm0 = fmaxf(rm0, __shfl_xor_sync(0xffffffffu, rm0, 1));
        rm0 = fmaxf(rm0, __shfl_xor_sync(0xffffffffu, rm0, 2));
        rm1 = fmaxf(rm1, __shfl_xor_sync(0xffffffffu, rm1, 1));
        rm1 = fmaxf(rm1, __shfl_xor_sync(0xffffffffu, rm1, 2));

        float mn0 = fmaxf(m0, rm0), mn1 = fmaxf(m1, rm1);
        float sc0 = __expf(m0 - mn0), sc1 = __expf(m1 - mn1);
        m0 = mn0; m1 = mn1;

        float rs0 = 0.f, rs1 = 0.f;
        uint32_t pf[8][2];
#pragma unroll
        for (int t = 0; t < 8; ++t) {
            float p00 = __expf(sacc[t][0] - mn0);
            float p01 = __expf(sacc[t][1] - mn0);
            float p10 = __expf(sacc[t][2] - mn1);
            float p11 = __expf(sacc[t][3] - mn1);
            rs0 += p00 + p01; rs1 += p10 + p11;
            __half2 h0 = __floats2half2_rn(p00, p01);
            __half2 h1 = __floats2half2_rn(p10, p11);
            pf[t][0] = *(uint32_t*)&h0;
            pf[t][1] = *(uint32_t*)&h1;
        }
        rs0 += __shfl_xor_sync(0xffffffffu, rs0, 1);
        rs0 += __shfl_xor_sync(0xffffffffu, rs0, 2);
        rs1 += __shfl_xor_sync(0xffffffffu, rs1, 1);
        rs1 += __shfl_xor_sync(0xffffffffu, rs1, 2);
        l0 = l0 * sc0 + rs0;
        l1 = l1 * sc1 + rs1;
#pragma unroll
        for (int t = 0; t < 8; ++t) {
            O[t][0] *= sc0; O[t][1] *= sc0;
            O[t][2] *= sc1; O[t][3] *= sc1;
        }

        // ---- O += P V ----  (V fragments via ldmatrix.trans)
#pragma unroll
        for (int s = 0; s < 4; ++s) {
            uint32_t a0 = pf[2 * s][0], a1 = pf[2 * s][1];
            uint32_t a2 = pf[2 * s + 1][0], a3 = pf[2 * s + 1][1];
            int vrow = 16 * s + ((jg & 1) << 3) + jr;   // key row
            int vcb  = (jg >> 1) << 3;                  // d col sub-offset
#pragma unroll
            for (int i = 0; i < 4; ++i) {
                uint32_t vf[4];
                ldsm_x4_t(vf, vsm + (uint32_t)(vrow * KV_PITCH + 16 * i + vcb) * 2);
                mma_f16(O[2 * i][0], O[2 * i][1], O[2 * i][2], O[2 * i][3],
                        a0, a1, a2, a3, vf[0], vf[1]);
                mma_f16(O[2 * i + 1][0], O[2 * i + 1][1], O[2 * i + 1][2], O[2 * i + 1][3],
                        a0, a1, a2, a3, vf[2], vf[3]);
            }
        }
    }

    float rl0 = (l0 > 0.f) ? (1.f / l0) : 0.f;
    float rl1 = (l1 > 0.f) ? (1.f / l1) : 0.f;
#pragma unroll
    for (int t = 0; t < 8; ++t) {
        int col = 8 * t + 2 * lk;
        *(__half2*)(Aout + baseO + (size_t)qi0 * HID + col)
            = __floats2half2_rn(O[t][0] * rl0, O[t][1] * rl0);
        *(__half2*)(Aout + baseO + (size_t)qi1 * HID + col)
            = __floats2half2_rn(O[t][2] * rl1, O[t][3] * rl1);
    }
}

// ---------------- final projection + sigmoid ----------------
__global__ __launch_bounds__(256) void final_kernel(
    const float* __restrict__ h, const float* __restrict__ Wp,
    const float* __restrict__ bp, float* __restrict__ out)
{
    int gtid = blockIdx.x * 256 + threadIdx.x;
    int row = gtid >> 5;
    int lane = gtid & 31;
    if (row >= MROWS) return;
    float s = 0.f;
    for (int k = lane; k < HID; k += 32)
        s = fmaf(h[(size_t)row * HID + k], Wp[k], s);
#pragma unroll
    for (int o = 16; o; o >>= 1) s += __shfl_xor_sync(0xffffffffu, s, o);
    if (lane == 0)
        out[row] = 1.f / (1.f + expf(-(s + bp[0])));
}

// ---------------- host orchestration ----------------
extern "C" void kernel_launch(void* const* d_in, const int* in_sizes, int n_in,
                              void* d_out, int out_size)
{
    const float* emb     = (const float*)d_in[0];
    const int*   amask   = (const int*)  d_in[1];
    const float* pos     = (const float*)d_in[2];
    const float* tok     = (const float*)d_in[3];
    const float* eln_g   = (const float*)d_in[4];
    const float* eln_b   = (const float*)d_in[5];
    const float* Wq      = (const float*)d_in[6];
    const float* bq      = (const float*)d_in[7];
    const float* Wk      = (const float*)d_in[8];
    const float* bk      = (const float*)d_in[9];
    const float* Wv      = (const float*)d_in[10];
    const float* bv      = (const float*)d_in[11];
    const float* Wo      = (const float*)d_in[12];
    const float* bo      = (const float*)d_in[13];
    const float* ln1_g   = (const float*)d_in[14];
    const float* ln1_b   = (const float*)d_in[15];
    const float* Wi      = (const float*)d_in[16];
    const float* bi      = (const float*)d_in[17];
    const float* Wf      = (const float*)d_in[18];
    const float* bf      = (const float*)d_in[19];
    const float* ln2_g   = (const float*)d_in[20];
    const float* ln2_b   = (const float*)d_in[21];
    const float* Wp      = (const float*)d_in[22];
    const float* bp      = (const float*)d_in[23];

    float  *h_, *t_, *bqkv_;
    __half *hb_, *qkv_, *ab_, *fb_, *wqkv_, *wo_, *wi_, *wf_;
    cudaGetSymbolAddress((void**)&h_,   g_h);
    cudaGetSymbolAddress((void**)&hb_,  g_hb);
    cudaGetSymbolAddress((void**)&qkv_, g_qkv);
    cudaGetSymbolAddress((void**)&ab_,  g_ab);
    cudaGetSymbolAddress((void**)&t_,   g_t);
    cudaGetSymbolAddress((void**)&fb_,  g_fb);
    cudaGetSymbolAddress((void**)&wqkv_, g_wqkv);
    cudaGetSymbolAddress((void**)&bqkv_, g_bqkv);
    cudaGetSymbolAddress((void**)&wo_,  g_wo);
    cudaGetSymbolAddress((void**)&wi_,  g_wi);
    cudaGetSymbolAddress((void**)&wf_,  g_wf);

    cudaFuncSetAttribute(gemm_f16_kernel,
                         cudaFuncAttributeMaxDynamicSharedMemorySize, GEMM_SMEM_BYTES);

    const size_t WSQ   = (size_t)HID * HID;
    const size_t WSI   = (size_t)HID * 4 * HID;
    const size_t WSQKV = (size_t)QS * HID;

    // ---- weight preprocessing: batched transposes (grid.z = layers) ----
    {
        dim3 blk(32, 8);
        dim3 gsq(HID / 32, HID / 32, LAYERS);
        transpose_h_kernel<<<gsq, blk>>>(Wq, wqkv_, HID, HID, WSQ, WSQKV);
        transpose_h_kernel<<<gsq, blk>>>(Wk, wqkv_ + (size_t)HID * HID, HID, HID, WSQ, WSQKV);
        transpose_h_kernel<<<gsq, blk>>>(Wv, wqkv_ + (size_t)2 * HID * HID, HID, HID, WSQ, WSQKV);
        transpose_h_kernel<<<gsq, blk>>>(Wo, wo_, HID, HID, WSQ, WSQ);
        dim3 gi(4 * HID / 32, HID / 32, LAYERS);
        transpose_h_kernel<<<gi, blk>>>(Wi, wi_, HID, 4 * HID, WSI, WSI);
        dim3 gf(HID / 32, 4 * HID / 32, LAYERS);
        transpose_h_kernel<<<gf, blk>>>(Wf, wf_, 4 * HID, HID, WSI, WSI);
        bias_qkv_kernel<<<(LAYERS * QS + 255) / 256, 256>>>(bq, bk, bv, bqkv_);
    }

    embed_ln_kernel<<<MROWS, 256>>>(emb, pos, tok, eln_g, eln_b, h_, hb_);

    for (int l = 0; l < LAYERS; ++l) {
        dim3 gqkv(QS / 128, MROWS / 128);
        gemm_f16_kernel<<<gqkv, 256, GEMM_SMEM_BYTES>>>(
            hb_, wqkv_ + l * WSQKV, bqkv_ + (size_t)l * QS, qkv_,
            MROWS, QS, HID, 2);

        dim3 ga(SS / 64, HEADS, BB);
        attn_tc_kernel<<<ga, 128>>>(qkv_, amask, ab_);

        dim3 g1(HID / 128, MROWS / 128);
        gemm_f16_kernel<<<g1, 256, GEMM_SMEM_BYTES>>>(
            ab_, wo_ + l * WSQ, bo + (size_t)l * HID, t_, MROWS, HID, HID, 0);
        add_ln_kernel<<<MROWS, 256>>>(h_, t_, ln1_g + l * HID, ln1_b + l * HID, h_, hb_);

        dim3 g2(4 * HID / 128, MROWS / 128);
        gemm_f16_kernel<<<g2, 256, GEMM_SMEM_BYTES>>>(
            hb_, wi_ + l * WSI, bi + (size_t)l * 4 * HID, fb_,
            MROWS, 4 * HID, HID, 1);
        gemm_f16_kernel<<<g1, 256, GEMM_SMEM_BYTES>>>(
            fb_, wf_ + l * WSI, bf + (size_t)l * HID, t_, MROWS, HID, 4 * HID, 0);
        add_ln_kernel<<<MROWS, 256>>>(h_, t_, ln2_g + l * HID, ln2_b + l * HID, h_, hb_);
    }

    final_kernel<<<(MROWS * 32 + 255) / 256, 256>>>(h_, Wp, bp, (float*)d_out);
}

// round 11
// speedup vs baseline: 1.8720x; 1.1646x over previous
#include <cuda_runtime.h>
#include <cuda_fp16.h>
#include <math.h>
#include <stdint.h>

// ---------------- problem constants ----------------
#define BB      2
#define SS      4096
#define HID     768
#define LAYERS  4
#define HEADS   12
#define HD      64
#define WIN     128          // one-sided window
#define MROWS   (BB*SS)      // 8192 token rows
#define QS      2304         // fused QKV row stride

// ---------------- scratch (device globals; no allocation) ----------------
__device__ __align__(256) float  g_h  [MROWS * HID];
__device__ __align__(256) __half g_hb [MROWS * HID];
__device__ __align__(256) __half g_qkv[MROWS * QS];
__device__ __align__(256) __half g_ab [MROWS * HID];
__device__ __align__(256) __half g_tb [MROWS * HID];       // GEMM out (half) pre-LN
__device__ __align__(256) __half g_fb [MROWS * 4 * HID];
// preprocessed weights: transposed to [N][K], half
__device__ __align__(256) __half g_wqkv[LAYERS * QS * HID];
__device__ __align__(256) float  g_bqkv[LAYERS * QS];
__device__ __align__(256) __half g_wo [LAYERS * HID * HID];
__device__ __align__(256) __half g_wi [LAYERS * 4 * HID * HID];
__device__ __align__(256) __half g_wf [LAYERS * HID * 4 * HID];

// =======================================================================
// helpers
// =======================================================================
__device__ __forceinline__ void mma_f16(
    float& d0, float& d1, float& d2, float& d3,
    uint32_t a0, uint32_t a1, uint32_t a2, uint32_t a3,
    uint32_t b0, uint32_t b1)
{
    asm volatile(
        "mma.sync.aligned.m16n8k16.row.col.f32.f16.f16.f32 "
        "{%0,%1,%2,%3}, {%4,%5,%6,%7}, {%8,%9}, {%0,%1,%2,%3};"
        : "+f"(d0), "+f"(d1), "+f"(d2), "+f"(d3)
        : "r"(a0), "r"(a1), "r"(a2), "r"(a3), "r"(b0), "r"(b1));
}
__device__ __forceinline__ void cp16(uint32_t dst, const void* src) {
    asm volatile("cp.async.cg.shared.global [%0], [%1], 16;"
                 :: "r"(dst), "l"(src));
}
__device__ __forceinline__ void ldsm_x4(uint32_t* r, uint32_t addr) {
    asm volatile("ldmatrix.sync.aligned.m8n8.x4.shared.b16 {%0,%1,%2,%3}, [%4];"
        : "=r"(r[0]), "=r"(r[1]), "=r"(r[2]), "=r"(r[3]) : "r"(addr));
}
__device__ __forceinline__ void ldsm_x4_t(uint32_t* r, uint32_t addr) {
    asm volatile("ldmatrix.sync.aligned.m8n8.x4.trans.shared.b16 {%0,%1,%2,%3}, [%4];"
        : "=r"(r[0]), "=r"(r[1]), "=r"(r[2]), "=r"(r[3]) : "r"(addr));
}

// =======================================================================
// fp16 mma.sync GEMM, cp.async 3-stage pipeline, ldmatrix fragment loads.
// act=0: fp32 C.  act=1: GELU, half C.  act=2: plain, half C.
// block 128x128, BK=32, 256 threads (8 warps), warp tile 32x64.
// smem tiles A,B both [128 rows][32 k] half, quad swizzle phys=q^((r>>1)&3).
// =======================================================================
#define TILE_BYTES (128*64)
#define STG_BYTES  (2*TILE_BYTES)
#define GEMM_SMEM_BYTES (3*STG_BYTES)    // 48 KB

__global__ __launch_bounds__(256, 2) void gemm_f16_kernel(
    const __half* __restrict__ A, const __half* __restrict__ Bw,
    const float* __restrict__ bias, void* __restrict__ Cout,
    int M, int N, int K, int act)
{
    extern __shared__ uint32_t smu[];
    uint32_t smem_base = (uint32_t)__cvta_generic_to_shared(smu);

    const int tid  = threadIdx.x;
    const int lane = tid & 31;
    const int wid  = tid >> 5;
    const int lm   = lane >> 2;
    const int lk   = lane & 3;
    const int jr   = lane & 7;
    const int jg   = lane >> 3;
    const int warp_m = (wid >> 1) * 32;
    const int warp_n = (wid & 1) * 64;
    const int bm = blockIdx.y * 128;
    const int bn = blockIdx.x * 128;

    const __half* Ag = A  + (size_t)bm * K;
    const __half* Bg = Bw + (size_t)bn * K;

    // cp.async mapping: thread covers rows r0 and r0+64, quad q0c
    const int r0 = tid >> 2, q0c = tid & 3;
    const int r1 = r0 + 64;
    const uint32_t offA0 = (uint32_t)(r0 * 64 + (q0c ^ ((r0 >> 1) & 3)) * 16);
    const uint32_t offA1 = (uint32_t)(r1 * 64 + (q0c ^ ((r1 >> 1) & 3)) * 16);

    // ldmatrix offsets (per thread, per k-step s)
    uint32_t offAf[2][2], offBf[4][2];
#pragma unroll
    for (int mt = 0; mt < 2; ++mt) {
        int row = warp_m + mt * 16 + ((jg & 1) << 3) + jr;
        int sw = (row >> 1) & 3;
#pragma unroll
        for (int s = 0; s < 2; ++s) {
            int quad = 2 * s + (jg >> 1);
            offAf[mt][s] = (uint32_t)(row * 64 + ((quad ^ sw) * 16));
        }
    }
#pragma unroll
    for (int ng = 0; ng < 4; ++ng) {
        int row = warp_n + (2 * ng + (jg >> 1)) * 8 + jr;
        int sw = (row >> 1) & 3;
#pragma unroll
        for (int s = 0; s < 2; ++s) {
            int quad = 2 * s + (jg & 1);
            offBf[ng][s] = (uint32_t)(TILE_BYTES + row * 64 + ((quad ^ sw) * 16));
        }
    }

    float acc[2][8][4];
#pragma unroll
    for (int mt = 0; mt < 2; ++mt)
#pragma unroll
        for (int nt = 0; nt < 8; ++nt)
#pragma unroll
            for (int c = 0; c < 4; ++c) acc[mt][nt][c] = 0.f;

    const int NC = K >> 5;

    auto issue = [&](int c, int stg) {
        uint32_t sA = smem_base + (uint32_t)stg * STG_BYTES;
        uint32_t sB = sA + TILE_BYTES;
        const __half* ag = Ag + c * 32;
        const __half* bg = Bg + c * 32;
        cp16(sA + offA0, ag + (size_t)r0 * K + q0c * 8);
        cp16(sA + offA1, ag + (size_t)r1 * K + q0c * 8);
        cp16(sB + offA0, bg + (size_t)r0 * K + q0c * 8);
        cp16(sB + offA1, bg + (size_t)r1 * K + q0c * 8);
    };

    issue(0, 0);
    asm volatile("cp.async.commit_group;" ::: "memory");
    if (NC > 1) issue(1, 1);
    asm volatile("cp.async.commit_group;" ::: "memory");

    for (int c = 0; c < NC; ++c) {
        asm volatile("cp.async.wait_group 1;" ::: "memory");
        __syncthreads();
        if (c + 2 < NC) issue(c + 2, (c + 2) % 3);
        asm volatile("cp.async.commit_group;" ::: "memory");

        const uint32_t stage = smem_base + (uint32_t)(c % 3) * STG_BYTES;
#pragma unroll
        for (int s = 0; s < 2; ++s) {
            uint32_t a[2][4];
            ldsm_x4(a[0], stage + offAf[0][s]);
            ldsm_x4(a[1], stage + offAf[1][s]);
            uint32_t bf[4][4];
#pragma unroll
            for (int ng = 0; ng < 4; ++ng)
                ldsm_x4(bf[ng], stage + offBf[ng][s]);
#pragma unroll
            for (int mt = 0; mt < 2; ++mt)
#pragma unroll
                for (int nt = 0; nt < 8; ++nt)
                    mma_f16(acc[mt][nt][0], acc[mt][nt][1],
                            acc[mt][nt][2], acc[mt][nt][3],
                            a[mt][0], a[mt][1], a[mt][2], a[mt][3],
                            bf[nt >> 1][(nt & 1) * 2],
                            bf[nt >> 1][(nt & 1) * 2 + 1]);
        }
    }

    // ---- epilogue ----
#pragma unroll
    for (int mt = 0; mt < 2; ++mt) {
        int row0 = bm + warp_m + mt * 16 + lm;
#pragma unroll
        for (int nt = 0; nt < 8; ++nt) {
            int col = bn + warp_n + nt * 8 + 2 * lk;
            float b0 = bias[col], b1 = bias[col + 1];
            float v0 = acc[mt][nt][0] + b0;
            float v1 = acc[mt][nt][1] + b1;
            float v2 = acc[mt][nt][2] + b0;
            float v3 = acc[mt][nt][3] + b1;
            if (act == 0) {
                float* C = (float*)Cout;
                *(float2*)(C + (size_t)row0 * N + col) = make_float2(v0, v1);
                *(float2*)(C + (size_t)(row0 + 8) * N + col) = make_float2(v2, v3);
            } else {
                if (act == 1) {
                    v0 = 0.5f * v0 * (1.0f + erff(v0 * 0.7071067811865476f));
                    v1 = 0.5f * v1 * (1.0f + erff(v1 * 0.7071067811865476f));
                    v2 = 0.5f * v2 * (1.0f + erff(v2 * 0.7071067811865476f));
                    v3 = 0.5f * v3 * (1.0f + erff(v3 * 0.7071067811865476f));
                }
                __half* C = (__half*)Cout;
                *(__half2*)(C + (size_t)row0 * N + col) = __floats2half2_rn(v0, v1);
                *(__half2*)(C + (size_t)(row0 + 8) * N + col) = __floats2half2_rn(v2, v3);
            }
        }
    }
}

// =======================================================================
// weight preprocessing: transpose fp32 [K,N] -> half [N,K], batched layers
// =======================================================================
__global__ __launch_bounds__(256) void transpose_h_kernel(
    const float* __restrict__ src, __half* __restrict__ dst, int K, int N,
    size_t sstride, size_t dstride)
{
    __shared__ float t[32][33];
    src += (size_t)blockIdx.z * sstride;
    dst += (size_t)blockIdx.z * dstride;
    int tx = threadIdx.x, ty = threadIdx.y;
    int x = blockIdx.x * 32 + tx;
    int y0 = blockIdx.y * 32;
#pragma unroll
    for (int j = 0; j < 32; j += 8)
        t[ty + j][tx] = src[(size_t)(y0 + ty + j) * N + x];
    __syncthreads();
    int n_out = blockIdx.x * 32 + ty;
#pragma unroll
    for (int j = 0; j < 32; j += 8)
        dst[(size_t)(n_out + j) * K + y0 + tx] = __float2half_rn(t[tx][ty + j]);
}

__global__ __launch_bounds__(256) void bias_qkv_kernel(
    const float* __restrict__ bq, const float* __restrict__ bk,
    const float* __restrict__ bv, float* __restrict__ bout)
{
    int idx = blockIdx.x * 256 + threadIdx.x;
    if (idx >= LAYERS * QS) return;
    int l = idx / QS, j = idx % QS;
    const float* src = (j < HID) ? bq : (j < 2 * HID) ? bk : bv;
    bout[idx] = src[(size_t)l * HID + (j % HID)];
}

// =======================================================================
// block reduction helper
// =======================================================================
__device__ __forceinline__ float block_sum(float v, float* sh) {
    __syncthreads();
    int lane = threadIdx.x & 31, w = threadIdx.x >> 5;
#pragma unroll
    for (int o = 16; o; o >>= 1) v += __shfl_xor_sync(0xffffffffu, v, o);
    if (lane == 0) sh[w] = v;
    __syncthreads();
    if (w == 0) {
        float t = (lane < 8) ? sh[lane] : 0.f;
#pragma unroll
        for (int o = 4; o; o >>= 1) t += __shfl_xor_sync(0xffffffffu, t, o);
        if (lane == 0) sh[0] = t;
    }
    __syncthreads();
    return sh[0];
}

// ---------------- embeddings + LN ----------------
__global__ __launch_bounds__(256) void embed_ln_kernel(
    const float* __restrict__ emb, const float* __restrict__ pos,
    const float* __restrict__ tok, const float* __restrict__ g,
    const float* __restrict__ b, float* __restrict__ out,
    __half* __restrict__ out_h)
{
    __shared__ float sh[8];
    int row = blockIdx.x;
    int s = row & (SS - 1);
    int tid = threadIdx.x;
    float x[3];
#pragma unroll
    for (int i = 0; i < 3; ++i) {
        int j = tid + i * 256;
        x[i] = emb[(size_t)row * HID + j] + pos[(size_t)(s + 1) * HID + j] + tok[j];
    }
    float mean = block_sum(x[0] + x[1] + x[2], sh) * (1.f / HID);
    float d2 = 0.f;
#pragma unroll
    for (int i = 0; i < 3; ++i) { float d = x[i] - mean; d2 += d * d; }
    float var = block_sum(d2, sh) * (1.f / HID);
    float rs = rsqrtf(var + 1e-12f);
#pragma unroll
    for (int i = 0; i < 3; ++i) {
        int j = tid + i * 256;
        float v = (x[i] - mean) * rs * g[j] + b[j];
        out[(size_t)row * HID + j] = v;
        out_h[(size_t)row * HID + j] = __float2half_rn(v);
    }
}

// ---------------- residual add + LN (xin now half) -------------
__global__ __launch_bounds__(256) void add_ln_kernel(
    const float* __restrict__ hin, const __half* __restrict__ xin,
    const float* __restrict__ g, const float* __restrict__ b,
    float* __restrict__ out, __half* __restrict__ out_h)
{
    __shared__ float sh[8];
    int row = blockIdx.x;
    int tid = threadIdx.x;
    float x[3];
#pragma unroll
    for (int i = 0; i < 3; ++i) {
        int j = tid + i * 256;
        x[i] = hin[(size_t)row * HID + j] + __half2float(xin[(size_t)row * HID + j]);
    }
    float mean = block_sum(x[0] + x[1] + x[2], sh) * (1.f / HID);
    float d2 = 0.f;
#pragma unroll
    for (int i = 0; i < 3; ++i) { float d = x[i] - mean; d2 += d * d; }
    float var = block_sum(d2, sh) * (1.f / HID);
    float rs = rsqrtf(var + 1e-12f);
#pragma unroll
    for (int i = 0; i < 3; ++i) {
        int j = tid + i * 256;
        float v = (x[i] - mean) * rs * g[j] + b[j];
        out[(size_t)row * HID + j] = v;
        out_h[(size_t)row * HID + j] = __float2half_rn(v);
    }
}

// =======================================================================
// tensor-core banded flash attention, ldmatrix edition (unchanged from R9)
// =======================================================================
#define KV_PITCH 72
__global__ __launch_bounds__(128) void attn_tc_kernel(
    const __half* __restrict__ QKV, const int* __restrict__ am,
    __half* __restrict__ Aout)
{
    __shared__ __half Qs[64 * KV_PITCH];
    __shared__ __half Ks[64 * KV_PITCH];
    __shared__ __half Vs[64 * KV_PITCH];
    __shared__ int kval[64];

    const int tid  = threadIdx.x;
    const int lane = tid & 31;
    const int w    = tid >> 5;
    const int lm   = lane >> 2;
    const int lk   = lane & 3;
    const int jr   = lane & 7;
    const int jg   = lane >> 3;
    const int q0 = blockIdx.x * 64, h = blockIdx.y, b = blockIdx.z;
    const size_t base  = ((size_t)b * SS) * QS + (size_t)h * HD;
    const size_t baseO = ((size_t)b * SS) * HID + (size_t)h * HD;

    const uint32_t qsm = (uint32_t)__cvta_generic_to_shared(Qs);
    const uint32_t ksm = (uint32_t)__cvta_generic_to_shared(Ks);
    const uint32_t vsm = (uint32_t)__cvta_generic_to_shared(Vs);

#pragma unroll
    for (int it = 0; it < 4; ++it) {
        int idx = tid + it * 128;
        int r = idx >> 3, c8 = (idx & 7) * 8;
        *(float4*)&Qs[r * KV_PITCH + c8] =
            *(const float4*)(QKV + base + (size_t)(q0 + r) * QS + c8);
    }
    __syncthreads();

    uint32_t qf[4][4];
    {
        int row = w * 16 + ((jg & 1) << 3) + jr;
        int coff = (jg >> 1) << 3;
#pragma unroll
        for (int s = 0; s < 4; ++s)
            ldsm_x4(qf[s], qsm + (uint32_t)(row * KV_PITCH + 16 * s + coff) * 2);
    }

    const int qi0 = q0 + w * 16 + lm;
    const int qi1 = qi0 + 8;

    float m0 = -INFINITY, m1 = -INFINITY, l0 = 0.f, l1 = 0.f;
    float O[8][4];
#pragma unroll
    for (int t = 0; t < 8; ++t)
#pragma unroll
        for (int c = 0; c < 4; ++c) O[t][c] = 0.f;

    for (int kt = 0; kt < 5; ++kt) {
        const int ks = q0 - 128 + kt * 64;
        __syncthreads();
#pragma unroll
        for (int it = 0; it < 4; ++it) {
            int idx = tid + it * 128;
            int r = idx >> 3, c8 = (idx & 7) * 8;
            int kj = ks + r;
            float4 kv = make_float4(0.f, 0.f, 0.f, 0.f);
            float4 vv = make_float4(0.f, 0.f, 0.f, 0.f);
            if ((unsigned)kj < (unsigned)SS) {
                kv = *(const float4*)(QKV + base + (size_t)kj * QS + HID + c8);
                vv = *(const float4*)(QKV + base + (size_t)kj * QS + 2 * HID + c8);
            }
            *(float4*)&Ks[r * KV_PITCH + c8] = kv;
            *(float4*)&Vs[r * KV_PITCH + c8] = vv;
        }
        if (tid < 64) {
            int kj = ks + tid;
            kval[tid] = ((unsigned)kj < (unsigned)SS) && (am[(size_t)b * SS + kj] != 0);
        }
        __syncthreads();

        float sacc[8][4];
#pragma unroll
        for (int t = 0; t < 8; ++t) {
#pragma unroll
            for (int c = 0; c < 4; ++c) sacc[t][c] = 0.f;
            uint32_t kf[8];
            int krow = 8 * t + jr;
            ldsm_x4(kf,     ksm + (uint32_t)(krow * KV_PITCH + 8 * jg) * 2);
            ldsm_x4(kf + 4, ksm + (uint32_t)(krow * KV_PITCH + 32 + 8 * jg) * 2);
#pragma unroll
            for (int s = 0; s < 4; ++s)
                mma_f16(sacc[t][0], sacc[t][1], sacc[t][2], sacc[t][3],
                        qf[s][0], qf[s][1], qf[s][2], qf[s][3],
                        kf[2 * s], kf[2 * s + 1]);
        }

        float rm0 = -INFINITY, rm1 = -INFINITY;
#pragma unroll
        for (int t = 0; t < 8; ++t) {
            int kc = 8 * t + 2 * lk;
            int kj0 = ks + kc, kj1 = kj0 + 1;
            bool v0 = kval[kc] != 0, v1 = kval[kc + 1] != 0;
            float s00 = (v0 && abs(kj0 - qi0) <= WIN) ? sacc[t][0] * 0.125f : -1e9f;
            float s01 = (v1 && abs(kj1 - qi0) <= WIN) ? sacc[t][1] * 0.125f : -1e9f;
            float s10 = (v0 && abs(kj0 - qi1) <= WIN) ? sacc[t][2] * 0.125f : -1e9f;
            float s11 = (v1 && abs(kj1 - qi1) <= WIN) ? sacc[t][3] * 0.125f : -1e9f;
            sacc[t][0] = s00; sacc[t][1] = s01; sacc[t][2] = s10; sacc[t][3] = s11;
            rm0 = fmaxf(rm0, fmaxf(s00, s01));
            rm1 = fmaxf(rm1, fmaxf(s10, s11));
        }
        rm0 = fmaxf(rm0, __shfl_xor_sync(0xffffffffu, rm0, 1));
        rm0 = fmaxf(rm0, __shfl_xor_sync(0xffffffffu, rm0, 2));
        rm1 = fmaxf(rm1, __shfl_xor_sync(0xffffffffu, rm1, 1));
        rm1 = fmaxf(rm1, __shfl_xor_sync(0xffffffffu, rm1, 2));

        float mn0 = fmaxf(m0, rm0), mn1 = fmaxf(m1, rm1);
        float sc0 = __expf(m0 - mn0), sc1 = __expf(m1 - mn1);
        m0 = mn0; m1 = mn1;

        float rs0 = 0.f, rs1 = 0.f;
        uint32_t pf[8][2];
#pragma unroll
        for (int t = 0; t < 8; ++t) {
            float p00 = __expf(sacc[t][0] - mn0);
            float p01 = __expf(sacc[t][1] - mn0);
            float p10 = __expf(sacc[t][2] - mn1);
            float p11 = __expf(sacc[t][3] - mn1);
            rs0 += p00 + p01; rs1 += p10 + p11;
            __half2 h0 = __floats2half2_rn(p00, p01);
            __half2 h1 = __floats2half2_rn(p10, p11);
            pf[t][0] = *(uint32_t*)&h0;
            pf[t][1] = *(uint32_t*)&h1;
        }
        rs0 += __shfl_xor_sync(0xffffffffu, rs0, 1);
        rs0 += __shfl_xor_sync(0xffffffffu, rs0, 2);
        rs1 += __shfl_xor_sync(0xffffffffu, rs1, 1);
        rs1 += __shfl_xor_sync(0xffffffffu, rs1, 2);
        l0 = l0 * sc0 + rs0;
        l1 = l1 * sc1 + rs1;
#pragma unroll
        for (int t = 0; t < 8; ++t) {
            O[t][0] *= sc0; O[t][1] *= sc0;
            O[t][2] *= sc1; O[t][3] *= sc1;
        }

#pragma unroll
        for (int s = 0; s < 4; ++s) {
            uint32_t a0 = pf[2 * s][0], a1 = pf[2 * s][1];
            uint32_t a2 = pf[2 * s + 1][0], a3 = pf[2 * s + 1][1];
            int vrow = 16 * s + ((jg & 1) << 3) + jr;
            int vcb  = (jg >> 1) << 3;
#pragma unroll
            for (int i = 0; i < 4; ++i) {
                uint32_t vf[4];
                ldsm_x4_t(vf, vsm + (uint32_t)(vrow * KV_PITCH + 16 * i + vcb) * 2);
                mma_f16(O[2 * i][0], O[2 * i][1], O[2 * i][2], O[2 * i][3],
                        a0, a1, a2, a3, vf[0], vf[1]);
                mma_f16(O[2 * i + 1][0], O[2 * i + 1][1], O[2 * i + 1][2], O[2 * i + 1][3],
                        a0, a1, a2, a3, vf[2], vf[3]);
            }
        }
    }

    float rl0 = (l0 > 0.f) ? (1.f / l0) : 0.f;
    float rl1 = (l1 > 0.f) ? (1.f / l1) : 0.f;
#pragma unroll
    for (int t = 0; t < 8; ++t) {
        int col = 8 * t + 2 * lk;
        *(__half2*)(Aout + baseO + (size_t)qi0 * HID + col)
            = __floats2half2_rn(O[t][0] * rl0, O[t][1] * rl0);
        *(__half2*)(Aout + baseO + (size_t)qi1 * HID + col)
            = __floats2half2_rn(O[t][2] * rl1, O[t][3] * rl1);
    }
}

// ---------------- final projection + sigmoid ----------------
__global__ __launch_bounds__(256) void final_kernel(
    const float* __restrict__ h, const float* __restrict__ Wp,
    const float* __restrict__ bp, float* __restrict__ out)
{
    int gtid = blockIdx.x * 256 + threadIdx.x;
    int row = gtid >> 5;
    int lane = gtid & 31;
    if (row >= MROWS) return;
    float s = 0.f;
    for (int k = lane; k < HID; k += 32)
        s = fmaf(h[(size_t)row * HID + k], Wp[k], s);
#pragma unroll
    for (int o = 16; o; o >>= 1) s += __shfl_xor_sync(0xffffffffu, s, o);
    if (lane == 0)
        out[row] = 1.f / (1.f + expf(-(s + bp[0])));
}

// ---------------- host orchestration ----------------
extern "C" void kernel_launch(void* const* d_in, const int* in_sizes, int n_in,
                              void* d_out, int out_size)
{
    const float* emb     = (const float*)d_in[0];
    const int*   amask   = (const int*)  d_in[1];
    const float* pos     = (const float*)d_in[2];
    const float* tok     = (const float*)d_in[3];
    const float* eln_g   = (const float*)d_in[4];
    const float* eln_b   = (const float*)d_in[5];
    const float* Wq      = (const float*)d_in[6];
    const float* bq      = (const float*)d_in[7];
    const float* Wk      = (const float*)d_in[8];
    const float* bk      = (const float*)d_in[9];
    const float* Wv      = (const float*)d_in[10];
    const float* bv      = (const float*)d_in[11];
    const float* Wo      = (const float*)d_in[12];
    const float* bo      = (const float*)d_in[13];
    const float* ln1_g   = (const float*)d_in[14];
    const float* ln1_b   = (const float*)d_in[15];
    const float* Wi      = (const float*)d_in[16];
    const float* bi      = (const float*)d_in[17];
    const float* Wf      = (const float*)d_in[18];
    const float* bf      = (const float*)d_in[19];
    const float* ln2_g   = (const float*)d_in[20];
    const float* ln2_b   = (const float*)d_in[21];
    const float* Wp      = (const float*)d_in[22];
    const float* bp      = (const float*)d_in[23];

    float  *h_, *bqkv_;
    __half *hb_, *qkv_, *ab_, *tb_, *fb_, *wqkv_, *wo_, *wi_, *wf_;
    cudaGetSymbolAddress((void**)&h_,   g_h);
    cudaGetSymbolAddress((void**)&hb_,  g_hb);
    cudaGetSymbolAddress((void**)&qkv_, g_qkv);
    cudaGetSymbolAddress((void**)&ab_,  g_ab);
    cudaGetSymbolAddress((void**)&tb_,  g_tb);
    cudaGetSymbolAddress((void**)&fb_,  g_fb);
    cudaGetSymbolAddress((void**)&wqkv_, g_wqkv);
    cudaGetSymbolAddress((void**)&bqkv_, g_bqkv);
    cudaGetSymbolAddress((void**)&wo_,  g_wo);
    cudaGetSymbolAddress((void**)&wi_,  g_wi);
    cudaGetSymbolAddress((void**)&wf_,  g_wf);

    cudaFuncSetAttribute(gemm_f16_kernel,
                         cudaFuncAttributeMaxDynamicSharedMemorySize, GEMM_SMEM_BYTES);

    const size_t WSQ   = (size_t)HID * HID;
    const size_t WSI   = (size_t)HID * 4 * HID;
    const size_t WSQKV = (size_t)QS * HID;

    // ---- weight preprocessing: batched transposes ----
    {
        dim3 blk(32, 8);
        dim3 gsq(HID / 32, HID / 32, LAYERS);
        transpose_h_kernel<<<gsq, blk>>>(Wq, wqkv_, HID, HID, WSQ, WSQKV);
        transpose_h_kernel<<<gsq, blk>>>(Wk, wqkv_ + (size_t)HID * HID, HID, HID, WSQ, WSQKV);
        transpose_h_kernel<<<gsq, blk>>>(Wv, wqkv_ + (size_t)2 * HID * HID, HID, HID, WSQ, WSQKV);
        transpose_h_kernel<<<gsq, blk>>>(Wo, wo_, HID, HID, WSQ, WSQ);
        dim3 gi(4 * HID / 32, HID / 32, LAYERS);
        transpose_h_kernel<<<gi, blk>>>(Wi, wi_, HID, 4 * HID, WSI, WSI);
        dim3 gf(HID / 32, 4 * HID / 32, LAYERS);
        transpose_h_kernel<<<gf, blk>>>(Wf, wf_, 4 * HID, HID, WSI, WSI);
        bias_qkv_kernel<<<(LAYERS * QS + 255) / 256, 256>>>(bq, bk, bv, bqkv_);
    }

    embed_ln_kernel<<<MROWS, 256>>>(emb, pos, tok, eln_g, eln_b, h_, hb_);

    for (int l = 0; l < LAYERS; ++l) {
        dim3 gqkv(QS / 128, MROWS / 128);
        gemm_f16_kernel<<<gqkv, 256, GEMM_SMEM_BYTES>>>(
            hb_, wqkv_ + l * WSQKV, bqkv_ + (size_t)l * QS, qkv_,
            MROWS, QS, HID, 2);

        dim3 ga(SS / 64, HEADS, BB);
        attn_tc_kernel<<<ga, 128>>>(qkv_, amask, ab_);

        dim3 g1(HID / 128, MROWS / 128);
        gemm_f16_kernel<<<g1, 256, GEMM_SMEM_BYTES>>>(
            ab_, wo_ + l * WSQ, bo + (size_t)l * HID, tb_, MROWS, HID, HID, 2);
        add_ln_kernel<<<MROWS, 256>>>(h_, tb_, ln1_g + l * HID, ln1_b + l * HID, h_, hb_);

        dim3 g2(4 * HID / 128, MROWS / 128);
        gemm_f16_kernel<<<g2, 256, GEMM_SMEM_BYTES>>>(
            hb_, wi_ + l * WSI, bi + (size_t)l * 4 * HID, fb_,
            MROWS, 4 * HID, HID, 1);
        gemm_f16_kernel<<<g1, 256, GEMM_SMEM_BYTES>>>(
            fb_, wf_ + l * WSI, bf + (size_t)l * HID, tb_, MROWS, HID, 4 * HID, 2);
        add_ln_kernel<<<MROWS, 256>>>(h_, tb_, ln2_g + l * HID, ln2_b + l * HID, h_, hb_);
    }

    final_kernel<<<(MROWS * 32 + 255) / 256, 256>>>(h_, Wp, bp, (float*)d_out);
}

// round 12
// speedup vs baseline: 2.0114x; 1.0745x over previous
#include <cuda_runtime.h>
#include <cuda_fp16.h>
#include <math.h>
#include <stdint.h>

// ---------------- problem constants ----------------
#define BB      2
#define SS      4096
#define HID     768
#define LAYERS  4
#define HEADS   12
#define HD      64
#define WIN     128          // one-sided window
#define MROWS   (BB*SS)      // 8192 token rows
#define QS      2304         // fused QKV row stride

// ---------------- scratch (device globals; no allocation) ----------------
__device__ __align__(256) float  g_h  [MROWS * HID];
__device__ __align__(256) __half g_hb [MROWS * HID];
__device__ __align__(256) __half g_qkv[MROWS * QS];
__device__ __align__(256) __half g_ab [MROWS * HID];
__device__ __align__(256) __half g_tb [MROWS * HID];
__device__ __align__(256) __half g_fb [MROWS * 4 * HID];
// preprocessed weights: transposed to [N][K], half
__device__ __align__(256) __half g_wqkv[LAYERS * QS * HID];
__device__ __align__(256) float  g_bqkv[LAYERS * QS];
__device__ __align__(256) __half g_wo [LAYERS * HID * HID];
__device__ __align__(256) __half g_wi [LAYERS * 4 * HID * HID];
__device__ __align__(256) __half g_wf [LAYERS * HID * 4 * HID];

// =======================================================================
// helpers
// =======================================================================
__device__ __forceinline__ void mma_f16(
    float& d0, float& d1, float& d2, float& d3,
    uint32_t a0, uint32_t a1, uint32_t a2, uint32_t a3,
    uint32_t b0, uint32_t b1)
{
    asm volatile(
        "mma.sync.aligned.m16n8k16.row.col.f32.f16.f16.f32 "
        "{%0,%1,%2,%3}, {%4,%5,%6,%7}, {%8,%9}, {%0,%1,%2,%3};"
        : "+f"(d0), "+f"(d1), "+f"(d2), "+f"(d3)
        : "r"(a0), "r"(a1), "r"(a2), "r"(a3), "r"(b0), "r"(b1));
}
__device__ __forceinline__ void cp16(uint32_t dst, const void* src) {
    asm volatile("cp.async.cg.shared.global [%0], [%1], 16;"
                 :: "r"(dst), "l"(src));
}
__device__ __forceinline__ void cp16z(uint32_t dst, const void* src, int srcbytes) {
    asm volatile("cp.async.cg.shared.global [%0], [%1], 16, %2;"
                 :: "r"(dst), "l"(src), "r"(srcbytes));
}
__device__ __forceinline__ void ldsm_x4(uint32_t* r, uint32_t addr) {
    asm volatile("ldmatrix.sync.aligned.m8n8.x4.shared.b16 {%0,%1,%2,%3}, [%4];"
        : "=r"(r[0]), "=r"(r[1]), "=r"(r[2]), "=r"(r[3]) : "r"(addr));
}
__device__ __forceinline__ void ldsm_x4_t(uint32_t* r, uint32_t addr) {
    asm volatile("ldmatrix.sync.aligned.m8n8.x4.trans.shared.b16 {%0,%1,%2,%3}, [%4];"
        : "=r"(r[0]), "=r"(r[1]), "=r"(r[2]), "=r"(r[3]) : "r"(addr));
}

// =======================================================================
// fp16 mma.sync GEMM, cp.async 4-stage pipeline, ldmatrix fragment loads.
// act=0: fp32 C.  act=1: GELU, half C.  act=2: plain, half C.
// block 128x128, BK=32, 256 threads (8 warps), warp tile 32x64.
// =======================================================================
#define TILE_BYTES (128*64)
#define STG_BYTES  (2*TILE_BYTES)
#define NSTAGE     4
#define GEMM_SMEM_BYTES (NSTAGE*STG_BYTES)    // 64 KB

__global__ __launch_bounds__(256, 2) void gemm_f16_kernel(
    const __half* __restrict__ A, const __half* __restrict__ Bw,
    const float* __restrict__ bias, void* __restrict__ Cout,
    int M, int N, int K, int act)
{
    extern __shared__ uint32_t smu[];
    uint32_t smem_base = (uint32_t)__cvta_generic_to_shared(smu);

    const int tid  = threadIdx.x;
    const int lane = tid & 31;
    const int wid  = tid >> 5;
    const int lm   = lane >> 2;
    const int lk   = lane & 3;
    const int jr   = lane & 7;
    const int jg   = lane >> 3;
    const int warp_m = (wid >> 1) * 32;
    const int warp_n = (wid & 1) * 64;
    const int bm = blockIdx.y * 128;
    const int bn = blockIdx.x * 128;

    const __half* Ag = A  + (size_t)bm * K;
    const __half* Bg = Bw + (size_t)bn * K;

    const int r0 = tid >> 2, q0c = tid & 3;
    const int r1 = r0 + 64;
    const uint32_t offA0 = (uint32_t)(r0 * 64 + (q0c ^ ((r0 >> 1) & 3)) * 16);
    const uint32_t offA1 = (uint32_t)(r1 * 64 + (q0c ^ ((r1 >> 1) & 3)) * 16);

    uint32_t offAf[2][2], offBf[4][2];
#pragma unroll
    for (int mt = 0; mt < 2; ++mt) {
        int row = warp_m + mt * 16 + ((jg & 1) << 3) + jr;
        int sw = (row >> 1) & 3;
#pragma unroll
        for (int s = 0; s < 2; ++s) {
            int quad = 2 * s + (jg >> 1);
            offAf[mt][s] = (uint32_t)(row * 64 + ((quad ^ sw) * 16));
        }
    }
#pragma unroll
    for (int ng = 0; ng < 4; ++ng) {
        int row = warp_n + (2 * ng + (jg >> 1)) * 8 + jr;
        int sw = (row >> 1) & 3;
#pragma unroll
        for (int s = 0; s < 2; ++s) {
            int quad = 2 * s + (jg & 1);
            offBf[ng][s] = (uint32_t)(TILE_BYTES + row * 64 + ((quad ^ sw) * 16));
        }
    }

    float acc[2][8][4];
#pragma unroll
    for (int mt = 0; mt < 2; ++mt)
#pragma unroll
        for (int nt = 0; nt < 8; ++nt)
#pragma unroll
            for (int c = 0; c < 4; ++c) acc[mt][nt][c] = 0.f;

    const int NC = K >> 5;

    auto issue = [&](int c, int stg) {
        uint32_t sA = smem_base + (uint32_t)stg * STG_BYTES;
        uint32_t sB = sA + TILE_BYTES;
        const __half* ag = Ag + c * 32;
        const __half* bg = Bg + c * 32;
        cp16(sA + offA0, ag + (size_t)r0 * K + q0c * 8);
        cp16(sA + offA1, ag + (size_t)r1 * K + q0c * 8);
        cp16(sB + offA0, bg + (size_t)r0 * K + q0c * 8);
        cp16(sB + offA1, bg + (size_t)r1 * K + q0c * 8);
    };

#pragma unroll
    for (int p = 0; p < 3; ++p) {
        if (p < NC) issue(p, p);
        asm volatile("cp.async.commit_group;" ::: "memory");
    }

    for (int c = 0; c < NC; ++c) {
        asm volatile("cp.async.wait_group 2;" ::: "memory");
        __syncthreads();
        if (c + 3 < NC) issue(c + 3, (c + 3) % NSTAGE);
        asm volatile("cp.async.commit_group;" ::: "memory");

        const uint32_t stage = smem_base + (uint32_t)(c % NSTAGE) * STG_BYTES;
#pragma unroll
        for (int s = 0; s < 2; ++s) {
            uint32_t a[2][4];
            ldsm_x4(a[0], stage + offAf[0][s]);
            ldsm_x4(a[1], stage + offAf[1][s]);
            uint32_t bf[4][4];
#pragma unroll
            for (int ng = 0; ng < 4; ++ng)
                ldsm_x4(bf[ng], stage + offBf[ng][s]);
#pragma unroll
            for (int mt = 0; mt < 2; ++mt)
#pragma unroll
                for (int nt = 0; nt < 8; ++nt)
                    mma_f16(acc[mt][nt][0], acc[mt][nt][1],
                            acc[mt][nt][2], acc[mt][nt][3],
                            a[mt][0], a[mt][1], a[mt][2], a[mt][3],
                            bf[nt >> 1][(nt & 1) * 2],
                            bf[nt >> 1][(nt & 1) * 2 + 1]);
        }
    }

    // ---- epilogue ----
#pragma unroll
    for (int mt = 0; mt < 2; ++mt) {
        int row0 = bm + warp_m + mt * 16 + lm;
#pragma unroll
        for (int nt = 0; nt < 8; ++nt) {
            int col = bn + warp_n + nt * 8 + 2 * lk;
            float b0 = bias[col], b1 = bias[col + 1];
            float v0 = acc[mt][nt][0] + b0;
            float v1 = acc[mt][nt][1] + b1;
            float v2 = acc[mt][nt][2] + b0;
            float v3 = acc[mt][nt][3] + b1;
            if (act == 0) {
                float* C = (float*)Cout;
                *(float2*)(C + (size_t)row0 * N + col) = make_float2(v0, v1);
                *(float2*)(C + (size_t)(row0 + 8) * N + col) = make_float2(v2, v3);
            } else {
                if (act == 1) {
                    v0 = 0.5f * v0 * (1.0f + erff(v0 * 0.7071067811865476f));
                    v1 = 0.5f * v1 * (1.0f + erff(v1 * 0.7071067811865476f));
                    v2 = 0.5f * v2 * (1.0f + erff(v2 * 0.7071067811865476f));
                    v3 = 0.5f * v3 * (1.0f + erff(v3 * 0.7071067811865476f));
                }
                __half* C = (__half*)Cout;
                *(__half2*)(C + (size_t)row0 * N + col) = __floats2half2_rn(v0, v1);
                *(__half2*)(C + (size_t)(row0 + 8) * N + col) = __floats2half2_rn(v2, v3);
            }
        }
    }
}

// =======================================================================
// weight preprocessing: transpose fp32 [K,N] -> half [N,K], batched layers
// =======================================================================
__global__ __launch_bounds__(256) void transpose_h_kernel(
    const float* __restrict__ src, __half* __restrict__ dst, int K, int N,
    size_t sstride, size_t dstride)
{
    __shared__ float t[32][33];
    src += (size_t)blockIdx.z * sstride;
    dst += (size_t)blockIdx.z * dstride;
    int tx = threadIdx.x, ty = threadIdx.y;
    int x = blockIdx.x * 32 + tx;
    int y0 = blockIdx.y * 32;
#pragma unroll
    for (int j = 0; j < 32; j += 8)
        t[ty + j][tx] = src[(size_t)(y0 + ty + j) * N + x];
    __syncthreads();
    int n_out = blockIdx.x * 32 + ty;
#pragma unroll
    for (int j = 0; j < 32; j += 8)
        dst[(size_t)(n_out + j) * K + y0 + tx] = __float2half_rn(t[tx][ty + j]);
}

__global__ __launch_bounds__(256) void bias_qkv_kernel(
    const float* __restrict__ bq, const float* __restrict__ bk,
    const float* __restrict__ bv, float* __restrict__ bout)
{
    int idx = blockIdx.x * 256 + threadIdx.x;
    if (idx >= LAYERS * QS) return;
    int l = idx / QS, j = idx % QS;
    const float* src = (j < HID) ? bq : (j < 2 * HID) ? bk : bv;
    bout[idx] = src[(size_t)l * HID + (j % HID)];
}

// =======================================================================
// block reduction helper
// =======================================================================
__device__ __forceinline__ float block_sum(float v, float* sh) {
    __syncthreads();
    int lane = threadIdx.x & 31, w = threadIdx.x >> 5;
#pragma unroll
    for (int o = 16; o; o >>= 1) v += __shfl_xor_sync(0xffffffffu, v, o);
    if (lane == 0) sh[w] = v;
    __syncthreads();
    if (w == 0) {
        float t = (lane < 8) ? sh[lane] : 0.f;
#pragma unroll
        for (int o = 4; o; o >>= 1) t += __shfl_xor_sync(0xffffffffu, t, o);
        if (lane == 0) sh[0] = t;
    }
    __syncthreads();
    return sh[0];
}

// ---------------- embeddings + LN ----------------
__global__ __launch_bounds__(256) void embed_ln_kernel(
    const float* __restrict__ emb, const float* __restrict__ pos,
    const float* __restrict__ tok, const float* __restrict__ g,
    const float* __restrict__ b, float* __restrict__ out,
    __half* __restrict__ out_h)
{
    __shared__ float sh[8];
    int row = blockIdx.x;
    int s = row & (SS - 1);
    int tid = threadIdx.x;
    float x[3];
#pragma unroll
    for (int i = 0; i < 3; ++i) {
        int j = tid + i * 256;
        x[i] = emb[(size_t)row * HID + j] + pos[(size_t)(s + 1) * HID + j] + tok[j];
    }
    float mean = block_sum(x[0] + x[1] + x[2], sh) * (1.f / HID);
    float d2 = 0.f;
#pragma unroll
    for (int i = 0; i < 3; ++i) { float d = x[i] - mean; d2 += d * d; }
    float var = block_sum(d2, sh) * (1.f / HID);
    float rs = rsqrtf(var + 1e-12f);
#pragma unroll
    for (int i = 0; i < 3; ++i) {
        int j = tid + i * 256;
        float v = (x[i] - mean) * rs * g[j] + b[j];
        out[(size_t)row * HID + j] = v;
        out_h[(size_t)row * HID + j] = __float2half_rn(v);
    }
}

// ---------------- residual add + LN (xin half) -------------
__global__ __launch_bounds__(256) void add_ln_kernel(
    const float* __restrict__ hin, const __half* __restrict__ xin,
    const float* __restrict__ g, const float* __restrict__ b,
    float* __restrict__ out, __half* __restrict__ out_h)
{
    __shared__ float sh[8];
    int row = blockIdx.x;
    int tid = threadIdx.x;
    float x[3];
#pragma unroll
    for (int i = 0; i < 3; ++i) {
        int j = tid + i * 256;
        x[i] = hin[(size_t)row * HID + j] + __half2float(xin[(size_t)row * HID + j]);
    }
    float mean = block_sum(x[0] + x[1] + x[2], sh) * (1.f / HID);
    float d2 = 0.f;
#pragma unroll
    for (int i = 0; i < 3; ++i) { float d = x[i] - mean; d2 += d * d; }
    float var = block_sum(d2, sh) * (1.f / HID);
    float rs = rsqrtf(var + 1e-12f);
#pragma unroll
    for (int i = 0; i < 3; ++i) {
        int j = tid + i * 256;
        float v = (x[i] - mean) * rs * g[j] + b[j];
        out[(size_t)row * HID + j] = v;
        out_h[(size_t)row * HID + j] = __float2half_rn(v);
    }
}

// =======================================================================
// tensor-core banded flash attention, cp.async double-buffered K/V.
// grid (S/64, H, B), 128 threads (4 warps), 64-query tile, 5x64 key tiles.
// =======================================================================
#define KV_PITCH 72
__global__ __launch_bounds__(128) void attn_tc_kernel(
    const __half* __restrict__ QKV, const int* __restrict__ am,
    __half* __restrict__ Aout)
{
    __shared__ __half Qs[64 * KV_PITCH];
    __shared__ __half Ks[2][64 * KV_PITCH];
    __shared__ __half Vs[2][64 * KV_PITCH];
    __shared__ int kvalAll[320];

    const int tid  = threadIdx.x;
    const int lane = tid & 31;
    const int w    = tid >> 5;
    const int lm   = lane >> 2;
    const int lk   = lane & 3;
    const int jr   = lane & 7;
    const int jg   = lane >> 3;
    const int q0 = blockIdx.x * 64, h = blockIdx.y, b = blockIdx.z;
    const size_t base  = ((size_t)b * SS) * QS + (size_t)h * HD;
    const size_t baseO = ((size_t)b * SS) * HID + (size_t)h * HD;

    const uint32_t qsm  = (uint32_t)__cvta_generic_to_shared(Qs);
    const uint32_t ksm0 = (uint32_t)__cvta_generic_to_shared(Ks[0]);
    const uint32_t vsm0 = (uint32_t)__cvta_generic_to_shared(Vs[0]);
    const uint32_t kbufB = (uint32_t)(64 * KV_PITCH * 2);   // bytes per buffer

    // per-thread cp.async mapping: row r8 = tid>>3, col c8 = (tid&7)*8 (one
    // 16B chunk); covers 16 rows per 128 threads -> 4 iterations of +16 rows.
    const int rr = tid >> 3, cc8 = (tid & 7) * 8;

    auto issue_kv = [&](int kt, int buf) {
        const int ks = q0 - 128 + kt * 64;
        uint32_t kd = ksm0 + (uint32_t)buf * kbufB;
        uint32_t vd = vsm0 + (uint32_t)buf * kbufB;
#pragma unroll
        for (int it = 0; it < 4; ++it) {
            int r = rr + it * 16;
            int kj = ks + r;
            int ok = ((unsigned)kj < (unsigned)SS) ? 16 : 0;
            int kjc = (kj < 0) ? 0 : ((kj >= SS) ? SS - 1 : kj);
            const __half* src = QKV + base + (size_t)kjc * QS + cc8;
            uint32_t off = (uint32_t)(r * KV_PITCH + cc8) * 2;
            cp16z(kd + off, src + HID, ok);
            cp16z(vd + off, src + 2 * HID, ok);
        }
    };

    // ---- stage Q tile + mask table + first K/V tile ----
#pragma unroll
    for (int it = 0; it < 4; ++it) {
        int idx = tid + it * 128;
        int r = idx >> 3, c8 = (idx & 7) * 8;
        *(float4*)&Qs[r * KV_PITCH + c8] =
            *(const float4*)(QKV + base + (size_t)(q0 + r) * QS + c8);
    }
    issue_kv(0, 0);
    asm volatile("cp.async.commit_group;" ::: "memory");
#pragma unroll
    for (int i = 0; i < 3; ++i) {
        int idx = tid + i * 128;
        if (idx < 320) {
            int kj = q0 - 128 + idx;
            kvalAll[idx] = ((unsigned)kj < (unsigned)SS) && (am[(size_t)b * SS + kj] != 0);
        }
    }
    __syncthreads();

    uint32_t qf[4][4];
    {
        int row = w * 16 + ((jg & 1) << 3) + jr;
        int coff = (jg >> 1) << 3;
#pragma unroll
        for (int s = 0; s < 4; ++s)
            ldsm_x4(qf[s], qsm + (uint32_t)(row * KV_PITCH + 16 * s + coff) * 2);
    }

    const int qi0 = q0 + w * 16 + lm;
    const int qi1 = qi0 + 8;

    float m0 = -INFINITY, m1 = -INFINITY, l0 = 0.f, l1 = 0.f;
    float O[8][4];
#pragma unroll
    for (int t = 0; t < 8; ++t)
#pragma unroll
        for (int c = 0; c < 4; ++c) O[t][c] = 0.f;

    for (int kt = 0; kt < 5; ++kt) {
        const int buf = kt & 1;
        const int ks = q0 - 128 + kt * 64;
        asm volatile("cp.async.wait_group 0;" ::: "memory");
        __syncthreads();
        if (kt + 1 < 5) issue_kv(kt + 1, buf ^ 1);
        asm volatile("cp.async.commit_group;" ::: "memory");

        const uint32_t ksm = ksm0 + (uint32_t)buf * kbufB;
        const uint32_t vsm = vsm0 + (uint32_t)buf * kbufB;

        // ---- S = Q K^T ----
        float sacc[8][4];
#pragma unroll
        for (int t = 0; t < 8; ++t) {
#pragma unroll
            for (int c = 0; c < 4; ++c) sacc[t][c] = 0.f;
            uint32_t kf[8];
            int krow = 8 * t + jr;
            ldsm_x4(kf,     ksm + (uint32_t)(krow * KV_PITCH + 8 * jg) * 2);
            ldsm_x4(kf + 4, ksm + (uint32_t)(krow * KV_PITCH + 32 + 8 * jg) * 2);
#pragma unroll
            for (int s = 0; s < 4; ++s)
                mma_f16(sacc[t][0], sacc[t][1], sacc[t][2], sacc[t][3],
                        qf[s][0], qf[s][1], qf[s][2], qf[s][3],
                        kf[2 * s], kf[2 * s + 1]);
        }

        // ---- mask + scale + row max ----
        const int moff = kt * 64;
        float rm0 = -INFINITY, rm1 = -INFINITY;
#pragma unroll
        for (int t = 0; t < 8; ++t) {
            int kc = 8 * t + 2 * lk;
            int kj0 = ks + kc, kj1 = kj0 + 1;
            bool v0 = kvalAll[moff + kc] != 0, v1 = kvalAll[moff + kc + 1] != 0;
            float s00 = (v0 && abs(kj0 - qi0) <= WIN) ? sacc[t][0] * 0.125f : -1e9f;
            float s01 = (v1 && abs(kj1 - qi0) <= WIN) ? sacc[t][1] * 0.125f : -1e9f;
            float s10 = (v0 && abs(kj0 - qi1) <= WIN) ? sacc[t][2] * 0.125f : -1e9f;
            float s11 = (v1 && abs(kj1 - qi1) <= WIN) ? sacc[t][3] * 0.125f : -1e9f;
            sacc[t][0] = s00; sacc[t][1] = s01; sacc[t][2] = s10; sacc[t][3] = s11;
            rm0 = fmaxf(rm0, fmaxf(s00, s01));
            rm1 = fmaxf(rm1, fmaxf(s10, s11));
        }
        rm0 = fmaxf(rm0, __shfl_xor_sync(0xffffffffu, rm0, 1));
        rm0 = fmaxf(rm0, __shfl_xor_sync(0xffffffffu, rm0, 2));
        rm1 = fmaxf(rm1, __shfl_xor_sync(0xffffffffu, rm1, 1));
        rm1 = fmaxf(rm1, __shfl_xor_sync(0xffffffffu, rm1, 2));

        float mn0 = fmaxf(m0, rm0), mn1 = fmaxf(m1, rm1);
        float sc0 = __expf(m0 - mn0), sc1 = __expf(m1 - mn1);
        m0 = mn0; m1 = mn1;

        float rs0 = 0.f, rs1 = 0.f;
        uint32_t pf[8][2];
#pragma unroll
        for (int t = 0; t < 8; ++t) {
            float p00 = __expf(sacc[t][0] - mn0);
            float p01 = __expf(sacc[t][1] - mn0);
            float p10 = __expf(sacc[t][2] - mn1);
            float p11 = __expf(sacc[t][3] - mn1);
            rs0 += p00 + p01; rs1 += p10 + p11;
            __half2 h0 = __floats2half2_rn(p00, p01);
            __half2 h1 = __floats2half2_rn(p10, p11);
            pf[t][0] = *(uint32_t*)&h0;
            pf[t][1] = *(uint32_t*)&h1;
        }
        rs0 += __shfl_xor_sync(0xffffffffu, rs0, 1);
        rs0 += __shfl_xor_sync(0xffffffffu, rs0, 2);
        rs1 += __shfl_xor_sync(0xffffffffu, rs1, 1);
        rs1 += __shfl_xor_sync(0xffffffffu, rs1, 2);
        l0 = l0 * sc0 + rs0;
        l1 = l1 * sc1 + rs1;
#pragma unroll
        for (int t = 0; t < 8; ++t) {
            O[t][0] *= sc0; O[t][1] *= sc0;
            O[t][2] *= sc1; O[t][3] *= sc1;
        }

        // ---- O += P V ----
#pragma unroll
        for (int s = 0; s < 4; ++s) {
            uint32_t a0 = pf[2 * s][0], a1 = pf[2 * s][1];
            uint32_t a2 = pf[2 * s + 1][0], a3 = pf[2 * s + 1][1];
            int vrow = 16 * s + ((jg & 1) << 3) + jr;
            int vcb  = (jg >> 1) << 3;
#pragma unroll
            for (int i = 0; i < 4; ++i) {
                uint32_t vf[4];
                ldsm_x4_t(vf, vsm + (uint32_t)(vrow * KV_PITCH + 16 * i + vcb) * 2);
                mma_f16(O[2 * i][0], O[2 * i][1], O[2 * i][2], O[2 * i][3],
                        a0, a1, a2, a3, vf[0], vf[1]);
                mma_f16(O[2 * i + 1][0], O[2 * i + 1][1], O[2 * i + 1][2], O[2 * i + 1][3],
                        a0, a1, a2, a3, vf[2], vf[3]);
            }
        }
    }

    float rl0 = (l0 > 0.f) ? (1.f / l0) : 0.f;
    float rl1 = (l1 > 0.f) ? (1.f / l1) : 0.f;
#pragma unroll
    for (int t = 0; t < 8; ++t) {
        int col = 8 * t + 2 * lk;
        *(__half2*)(Aout + baseO + (size_t)qi0 * HID + col)
            = __floats2half2_rn(O[t][0] * rl0, O[t][1] * rl0);
        *(__half2*)(Aout + baseO + (size_t)qi1 * HID + col)
            = __floats2half2_rn(O[t][2] * rl1, O[t][3] * rl1);
    }
}

// ---------------- final projection + sigmoid ----------------
__global__ __launch_bounds__(256) void final_kernel(
    const float* __restrict__ h, const float* __restrict__ Wp,
    const float* __restrict__ bp, float* __restrict__ out)
{
    int gtid = blockIdx.x * 256 + threadIdx.x;
    int row = gtid >> 5;
    int lane = gtid & 31;
    if (row >= MROWS) return;
    float s = 0.f;
    for (int k = lane; k < HID; k += 32)
        s = fmaf(h[(size_t)row * HID + k], Wp[k], s);
#pragma unroll
    for (int o = 16; o; o >>= 1) s += __shfl_xor_sync(0xffffffffu, s, o);
    if (lane == 0)
        out[row] = 1.f / (1.f + expf(-(s + bp[0])));
}

// ---------------- host orchestration ----------------
extern "C" void kernel_launch(void* const* d_in, const int* in_sizes, int n_in,
                              void* d_out, int out_size)
{
    const float* emb     = (const float*)d_in[0];
    const int*   amask   = (const int*)  d_in[1];
    const float* pos     = (const float*)d_in[2];
    const float* tok     = (const float*)d_in[3];
    const float* eln_g   = (const float*)d_in[4];
    const float* eln_b   = (const float*)d_in[5];
    const float* Wq      = (const float*)d_in[6];
    const float* bq      = (const float*)d_in[7];
    const float* Wk      = (const float*)d_in[8];
    const float* bk      = (const float*)d_in[9];
    const float* Wv      = (const float*)d_in[10];
    const float* bv      = (const float*)d_in[11];
    const float* Wo      = (const float*)d_in[12];
    const float* bo      = (const float*)d_in[13];
    const float* ln1_g   = (const float*)d_in[14];
    const float* ln1_b   = (const float*)d_in[15];
    const float* Wi      = (const float*)d_in[16];
    const float* bi      = (const float*)d_in[17];
    const float* Wf      = (const float*)d_in[18];
    const float* bf      = (const float*)d_in[19];
    const float* ln2_g   = (const float*)d_in[20];
    const float* ln2_b   = (const float*)d_in[21];
    const float* Wp      = (const float*)d_in[22];
    const float* bp      = (const float*)d_in[23];

    float  *h_, *bqkv_;
    __half *hb_, *qkv_, *ab_, *tb_, *fb_, *wqkv_, *wo_, *wi_, *wf_;
    cudaGetSymbolAddress((void**)&h_,   g_h);
    cudaGetSymbolAddress((void**)&hb_,  g_hb);
    cudaGetSymbolAddress((void**)&qkv_, g_qkv);
    cudaGetSymbolAddress((void**)&ab_,  g_ab);
    cudaGetSymbolAddress((void**)&tb_,  g_tb);
    cudaGetSymbolAddress((void**)&fb_,  g_fb);
    cudaGetSymbolAddress((void**)&wqkv_, g_wqkv);
    cudaGetSymbolAddress((void**)&bqkv_, g_bqkv);
    cudaGetSymbolAddress((void**)&wo_,  g_wo);
    cudaGetSymbolAddress((void**)&wi_,  g_wi);
    cudaGetSymbolAddress((void**)&wf_,  g_wf);

    cudaFuncSetAttribute(gemm_f16_kernel,
                         cudaFuncAttributeMaxDynamicSharedMemorySize, GEMM_SMEM_BYTES);

    const size_t WSQ   = (size_t)HID * HID;
    const size_t WSI   = (size_t)HID * 4 * HID;
    const size_t WSQKV = (size_t)QS * HID;

    // ---- weight preprocessing: batched transposes ----
    {
        dim3 blk(32, 8);
        dim3 gsq(HID / 32, HID / 32, LAYERS);
        transpose_h_kernel<<<gsq, blk>>>(Wq, wqkv_, HID, HID, WSQ, WSQKV);
        transpose_h_kernel<<<gsq, blk>>>(Wk, wqkv_ + (size_t)HID * HID, HID, HID, WSQ, WSQKV);
        transpose_h_kernel<<<gsq, blk>>>(Wv, wqkv_ + (size_t)2 * HID * HID, HID, HID, WSQ, WSQKV);
        transpose_h_kernel<<<gsq, blk>>>(Wo, wo_, HID, HID, WSQ, WSQ);
        dim3 gi(4 * HID / 32, HID / 32, LAYERS);
        transpose_h_kernel<<<gi, blk>>>(Wi, wi_, HID, 4 * HID, WSI, WSI);
        dim3 gf(HID / 32, 4 * HID / 32, LAYERS);
        transpose_h_kernel<<<gf, blk>>>(Wf, wf_, 4 * HID, HID, WSI, WSI);
        bias_qkv_kernel<<<(LAYERS * QS + 255) / 256, 256>>>(bq, bk, bv, bqkv_);
    }

    embed_ln_kernel<<<MROWS, 256>>>(emb, pos, tok, eln_g, eln_b, h_, hb_);

    for (int l = 0; l < LAYERS; ++l) {
        dim3 gqkv(QS / 128, MROWS / 128);
        gemm_f16_kernel<<<gqkv, 256, GEMM_SMEM_BYTES>>>(
            hb_, wqkv_ + l * WSQKV, bqkv_ + (size_t)l * QS, qkv_,
            MROWS, QS, HID, 2);

        dim3 ga(SS / 64, HEADS, BB);
        attn_tc_kernel<<<ga, 128>>>(qkv_, amask, ab_);

        dim3 g1(HID / 128, MROWS / 128);
        gemm_f16_kernel<<<g1, 256, GEMM_SMEM_BYTES>>>(
            ab_, wo_ + l * WSQ, bo + (size_t)l * HID, tb_, MROWS, HID, HID, 2);
        add_ln_kernel<<<MROWS, 256>>>(h_, tb_, ln1_g + l * HID, ln1_b + l * HID, h_, hb_);

        dim3 g2(4 * HID / 128, MROWS / 128);
        gemm_f16_kernel<<<g2, 256, GEMM_SMEM_BYTES>>>(
            hb_, wi_ + l * WSI, bi + (size_t)l * 4 * HID, fb_,
            MROWS, 4 * HID, HID, 1);
        gemm_f16_kernel<<<g1, 256, GEMM_SMEM_BYTES>>>(
            fb_, wf_ + l * WSI, bf + (size_t)l * HID, tb_, MROWS, HID, 4 * HID, 2);
        add_ln_kernel<<<MROWS, 256>>>(h_, tb_, ln2_g + l * HID, ln2_b + l * HID, h_, hb_);
    }

    final_kernel<<<(MROWS * 32 + 255) / 256, 256>>>(h_, Wp, bp, (float*)d_out);
}